// round 11
// baseline (speedup 1.0000x reference)
#include <cuda_runtime.h>
#include <cuda_bf16.h>
#include <mma.h>
#include <math.h>

using namespace nvcuda;

#define B_   2
#define S_   256
#define D_   1024
#define H_   8
#define L_   16
#define FF_  2048
#define V_   50257
#define NPV_ 50432            // V padded to multiple of 256 for plane layout
#define HD_  128
#define SB_  (S_*B_)          // 512
#define SBD_ (SB_*D_)         // 524288

typedef __nv_bfloat16 bf16;

// ---------------- fp32 masters ----------------------------------------------------
static __device__ float g_x0[SBD_];
static __device__ float g_lo[L_*SBD_];
static __device__ float g_sc[15*16*S_*S_];
static __device__ float g_xa[SBD_];
static __device__ float g_t2[SBD_];
static __device__ float g_dw[L_*16];

// ---------------- bf16 hi/lo activation planes ------------------------------------
static __device__ __align__(16) bf16 g_x0h[SBD_],  g_x0l[SBD_];
static __device__ __align__(16) bf16 g_loh[L_*SBD_], g_lol[L_*SBD_];
static __device__ __align__(16) bf16 g_qh[SBD_],   g_ql[SBD_];
static __device__ __align__(16) bf16 g_kh[15*SBD_], g_kl[15*SBD_];
static __device__ __align__(16) bf16 g_vh[15*SBD_], g_vl[15*SBD_];
static __device__ __align__(16) bf16 g_sch[15*16*S_*S_], g_scl[15*16*S_*S_];
static __device__ __align__(16) bf16 g_combh[SBD_], g_combl[SBD_];
static __device__ __align__(16) bf16 g_xah[SBD_],  g_xal[SBD_];
static __device__ __align__(16) bf16 g_sph[SBD_];
static __device__ __align__(16) bf16 g_tffh[SB_*FF_], g_tffl[SB_*FF_];

// ---------------- bf16 hi/lo weight planes ----------------------------------------
static __device__ __align__(16) bf16 g_wqh[L_*D_*D_],  g_wql[L_*D_*D_];
static __device__ __align__(16) bf16 g_wkh[L_*D_*D_],  g_wkl[L_*D_*D_];
static __device__ __align__(16) bf16 g_wvh[L_*D_*D_],  g_wvl[L_*D_*D_];
static __device__ __align__(16) bf16 g_woh[L_*D_*D_],  g_wol[L_*D_*D_];
static __device__ __align__(16) bf16 g_wsh[L_*D_*D_],  g_wsl[L_*D_*D_];
static __device__ __align__(16) bf16 g_w1h[L_*D_*FF_], g_w1l[L_*D_*FF_];
static __device__ __align__(16) bf16 g_w2h[L_*FF_*D_], g_w2l[L_*FF_*D_];
static __device__ __align__(16) bf16 g_wouth[D_*NPV_], g_woutl[D_*NPV_];

// ================== split helpers =================================================
__device__ __forceinline__ void cvt_store4(float4 v, bf16* hp, bf16* lp)
{
    bf16 h0 = __float2bfloat16(v.x), h1 = __float2bfloat16(v.y);
    bf16 h2 = __float2bfloat16(v.z), h3 = __float2bfloat16(v.w);
    bf16 l0 = __float2bfloat16(v.x - __bfloat162float(h0));
    bf16 l1 = __float2bfloat16(v.y - __bfloat162float(h1));
    bf16 l2 = __float2bfloat16(v.z - __bfloat162float(h2));
    bf16 l3 = __float2bfloat16(v.w - __bfloat162float(h3));
    __nv_bfloat162 a; a.x = h0; a.y = h1;
    __nv_bfloat162 b; b.x = h2; b.y = h3;
    __nv_bfloat162 c; c.x = l0; c.y = l1;
    __nv_bfloat162 d; d.x = l2; d.y = l3;
    *(__nv_bfloat162*)(hp)   = a;  *(__nv_bfloat162*)(hp+2) = b;
    *(__nv_bfloat162*)(lp)   = c;  *(__nv_bfloat162*)(lp+2) = d;
}
__device__ __forceinline__ void cvt_store1(float x, bf16* hp, bf16* lp)
{
    bf16 h = __float2bfloat16(x);
    *hp = h;
    *lp = __float2bfloat16(x - __bfloat162float(h));
}

// ================== weight conversion (once per launch, memory-bound) =============
__global__ void __launch_bounds__(256) cvtw_kernel(const float* __restrict__ src,
                                                   bf16* __restrict__ h,
                                                   bf16* __restrict__ l, int n)
{
    int i = (blockIdx.x*256 + threadIdx.x)*4;
    if (i >= n) return;
    float4 v = *(const float4*)(src + i);
    cvt_store4(v, h + i, l + i);
}
__global__ void __launch_bounds__(256) cvtwout_kernel(const float* __restrict__ src,
                                                      bf16* __restrict__ h,
                                                      bf16* __restrict__ l)
{
    int n = blockIdx.x*256 + threadIdx.x;
    int row = blockIdx.y;
    float x = (n < V_) ? src[(size_t)row*V_ + n] : 0.f;
    cvt_store1(x, &h[(size_t)row*NPV_ + n], &l[(size_t)row*NPV_ + n]);
}

// ================== GEMM core: bf16-plane inputs (R6 body, static smem) ===========
// Block 128x128x32, 8 warps (2m x 4n), warp tile 64x32 (4x2 wmma 16x16x16).
// OM: 0 = fp32 out (bias,relu,OUTBS,bounds), 1 = bf16 hi/lo plane out.
// AEX: A exact bf16 (skip Al plane + Al*Bh term).
template<int OM, bool RELU, bool OUTBS, bool AEX>
__device__ __forceinline__ void gemm_core(
    int N, int K,
    const bf16* __restrict__ Ahg, const bf16* __restrict__ Alg, int lda,
    const bf16* __restrict__ Bhg, const bf16* __restrict__ Blg, int ldb,
    const float* __restrict__ bias,
    float* __restrict__ Cf, bf16* __restrict__ Ch, bf16* __restrict__ Cl, int ldc,
    int m0, int n0, char* smraw)
{
    bf16* sAh = (bf16*)(smraw);
    bf16* sAl = (bf16*)(smraw + 10240);
    bf16* sBh = (bf16*)(smraw + 20480);
    bf16* sBl = (bf16*)(smraw + 29184);
    float* stage = (float*)smraw;

    int tid = threadIdx.x;
    int warp = tid >> 5;
    int wm = warp >> 2, wn = warp & 3;

    wmma::fragment<wmma::accumulator, 16, 16, 16, float> acc[4][2];
    #pragma unroll
    for (int i = 0; i < 4; i++)
        #pragma unroll
        for (int j = 0; j < 2; j++)
            wmma::fill_fragment(acc[i][j], 0.0f);

    int arow = tid >> 1, akq = (tid & 1) << 4;
    int bkr = tid >> 3, bnq = (tid & 7) << 4;

    const bf16* Ah0 = Ahg + (size_t)(m0 + arow)*lda + akq;
    const bf16* Al0 = AEX ? Ah0 : (Alg + (size_t)(m0 + arow)*lda + akq);

    for (int k0 = 0; k0 < K; k0 += 32) {
        {
            const uint4* ph = (const uint4*)(Ah0 + k0);
            uint4 h0 = ph[0], h1 = ph[1];
            ((uint4*)(sAh + arow*40 + akq))[0] = h0;
            ((uint4*)(sAh + arow*40 + akq))[1] = h1;
            if (!AEX) {
                const uint4* pl = (const uint4*)(Al0 + k0);
                uint4 l0 = pl[0], l1 = pl[1];
                ((uint4*)(sAl + arow*40 + akq))[0] = l0;
                ((uint4*)(sAl + arow*40 + akq))[1] = l1;
            }
        }
        {
            const uint4* ph = (const uint4*)(Bhg + (size_t)(k0 + bkr)*ldb + n0 + bnq);
            const uint4* pl = (const uint4*)(Blg + (size_t)(k0 + bkr)*ldb + n0 + bnq);
            uint4 h0 = ph[0], h1 = ph[1];
            uint4 l0 = pl[0], l1 = pl[1];
            ((uint4*)(sBh + bkr*136 + bnq))[0] = h0;
            ((uint4*)(sBh + bkr*136 + bnq))[1] = h1;
            ((uint4*)(sBl + bkr*136 + bnq))[0] = l0;
            ((uint4*)(sBl + bkr*136 + bnq))[1] = l1;
        }
        __syncthreads();
        #pragma unroll
        for (int kk = 0; kk < 32; kk += 16) {
            wmma::fragment<wmma::matrix_b, 16, 16, 16, bf16, wmma::row_major> fbh[2], fbl[2];
            #pragma unroll
            for (int j = 0; j < 2; j++) {
                wmma::load_matrix_sync(fbh[j], &sBh[kk*136 + wn*32 + j*16], 136);
                wmma::load_matrix_sync(fbl[j], &sBl[kk*136 + wn*32 + j*16], 136);
            }
            #pragma unroll
            for (int i = 0; i < 4; i++) {
                wmma::fragment<wmma::matrix_a, 16, 16, 16, bf16, wmma::row_major> fah, fal;
                wmma::load_matrix_sync(fah, &sAh[(wm*64 + i*16)*40 + kk], 40);
                if (!AEX) wmma::load_matrix_sync(fal, &sAl[(wm*64 + i*16)*40 + kk], 40);
                #pragma unroll
                for (int j = 0; j < 2; j++) {
                    wmma::mma_sync(acc[i][j], fah, fbh[j], acc[i][j]);
                    wmma::mma_sync(acc[i][j], fah, fbl[j], acc[i][j]);
                    if (!AEX) wmma::mma_sync(acc[i][j], fal, fbh[j], acc[i][j]);
                }
            }
        }
        __syncthreads();
    }

    // ---- staged epilogue ----
    const bool valigned = ((ldc & 3) == 0);
    #pragma unroll
    for (int ph = 0; ph < 2; ph++) {
        if (wm == ph) {
            #pragma unroll
            for (int i = 0; i < 4; i++)
                #pragma unroll
                for (int j = 0; j < 2; j++)
                    wmma::store_matrix_sync(&stage[(i*16)*132 + wn*32 + j*16],
                                            acc[i][j], 132, wmma::mem_row_major);
        }
        __syncthreads();
        int r = tid >> 2;
        int c0 = (tid & 3) << 5;
        int m = m0 + ph*64 + r;
        int orow = OUTBS ? ((m & 1)*S_ + (m >> 1)) : m;
        const float* srow = stage + r*132 + c0;
        int nb = n0 + c0;
        if (OM == 1) {
            bf16* hrow = Ch + (size_t)orow*ldc;
            bf16* lrow = Cl + (size_t)orow*ldc;
            #pragma unroll
            for (int g = 0; g < 8; g++) {
                float4 v = *(const float4*)(srow + g*4);
                float4 bb = *(const float4*)(bias + nb + g*4);
                v.x += bb.x; v.y += bb.y; v.z += bb.z; v.w += bb.w;
                if (RELU) {
                    v.x = fmaxf(v.x, 0.f); v.y = fmaxf(v.y, 0.f);
                    v.z = fmaxf(v.z, 0.f); v.w = fmaxf(v.w, 0.f);
                }
                cvt_store4(v, hrow + nb + g*4, lrow + nb + g*4);
            }
        } else {
            float* crow = Cf + (size_t)orow*ldc;
            if (valigned && nb + 32 <= N) {
                #pragma unroll
                for (int g = 0; g < 8; g++) {
                    float4 v = *(const float4*)(srow + g*4);
                    float4 bb = *(const float4*)(bias + nb + g*4);
                    v.x += bb.x; v.y += bb.y; v.z += bb.z; v.w += bb.w;
                    if (RELU) {
                        v.x = fmaxf(v.x, 0.f); v.y = fmaxf(v.y, 0.f);
                        v.z = fmaxf(v.z, 0.f); v.w = fmaxf(v.w, 0.f);
                    }
                    *(float4*)(crow + nb + g*4) = v;
                }
            } else {
                for (int g = 0; g < 32; g++) {
                    int n = nb + g;
                    if (n < N) {
                        float v = srow[g] + bias[n];
                        if (RELU) v = fmaxf(v, 0.f);
                        crow[n] = v;
                    }
                }
            }
        }
        __syncthreads();
    }
}

template<int OM, bool RELU, bool OUTBS, bool AEX>
__global__ void __launch_bounds__(256) gemm_wmma(
    int N, int K,
    const bf16* __restrict__ Ahg, const bf16* __restrict__ Alg, int lda,
    const bf16* __restrict__ Bhg, const bf16* __restrict__ Blg, int ldb,
    const float* __restrict__ bias,
    float* __restrict__ Cf, bf16* __restrict__ Ch, bf16* __restrict__ Cl, int ldc)
{
    __shared__ __align__(16) char smraw[37888];
    gemm_core<OM, RELU, OUTBS, AEX>(N, K, Ahg, Alg, lda, Bhg, Blg, ldb, bias,
                                    Cf, Ch, Cl, ldc,
                                    blockIdx.y << 7, blockIdx.x << 7, smraw);
}

// ================== merged K+V projection (one launch, uniform, no early-exit) ====
// grid (16, nsrc*4): blockIdx.x < 8 -> K column tile n0=x*128; else V tile n0=(x-8)*128.
__global__ void __launch_bounds__(256) kv_wmma(
    const bf16* __restrict__ sbh, const bf16* __restrict__ sbl,
    const bf16* __restrict__ wkh, const bf16* __restrict__ wkl,
    const bf16* __restrict__ wvh, const bf16* __restrict__ wvl,
    const float* __restrict__ bk, const float* __restrict__ bv,
    bf16* __restrict__ kh, bf16* __restrict__ kl,
    bf16* __restrict__ vh, bf16* __restrict__ vl)
{
    __shared__ __align__(16) char smraw[37888];
    int x = blockIdx.x;
    bool isV = (x >= 8);
    int n0 = (x & 7) << 7;
    const bf16* Bh = isV ? wvh : wkh;
    const bf16* Bl = isV ? wvl : wkl;
    const float* bias = isV ? bv : bk;
    bf16* Ch = isV ? vh : kh;
    bf16* Cl = isV ? vl : kl;
    gemm_core<1, false, false, false>(D_, D_, sbh, sbl, D_, Bh, Bl, D_, bias,
                                      nullptr, Ch, Cl, D_,
                                      blockIdx.y << 7, n0, smraw);
}

// ================== QK scores (NT): P = scale * Q.K^T, plane inputs (R6) ==========
__global__ void __launch_bounds__(256) qk_wmma(
    const bf16* __restrict__ Qh, const bf16* __restrict__ Ql,
    const bf16* __restrict__ Kh, const bf16* __restrict__ Kl,
    float* __restrict__ P)
{
    __shared__ __align__(16) char smraw[40960];
    bf16* sAh = (bf16*)(smraw);
    bf16* sAl = (bf16*)(smraw + 10240);
    bf16* sBh = (bf16*)(smraw + 20480);
    bf16* sBl = (bf16*)(smraw + 30720);

    int z = blockIdx.z;
    int src = z >> 4, bh = z & 15;
    const bf16* Aqh = Qh + bh*HD_;
    const bf16* Aql = Ql + bh*HD_;
    const bf16* Bkh = Kh + (size_t)src*SBD_ + bh*HD_;
    const bf16* Bkl = Kl + (size_t)src*SBD_ + bh*HD_;
    float* Cp = P + (size_t)z*S_*S_;

    int tid = threadIdx.x;
    int warp = tid >> 5;
    int wm = warp >> 2, wn = warp & 3;
    int m0 = blockIdx.y << 7, n0 = blockIdx.x << 7;

    wmma::fragment<wmma::accumulator, 16, 16, 16, float> acc[4][2];
    #pragma unroll
    for (int i = 0; i < 4; i++)
        #pragma unroll
        for (int j = 0; j < 2; j++)
            wmma::fill_fragment(acc[i][j], 0.0f);

    int arow = tid >> 1, akq = (tid & 1) << 4;

    for (int k0 = 0; k0 < HD_; k0 += 32) {
        size_t aoff = (size_t)(m0 + arow)*(B_*D_) + k0 + akq;
        size_t boff = (size_t)(n0 + arow)*(B_*D_) + k0 + akq;
        uint4 ah0 = ((const uint4*)(Aqh + aoff))[0], ah1 = ((const uint4*)(Aqh + aoff))[1];
        uint4 al0 = ((const uint4*)(Aql + aoff))[0], al1 = ((const uint4*)(Aql + aoff))[1];
        uint4 bh0 = ((const uint4*)(Bkh + boff))[0], bh1 = ((const uint4*)(Bkh + boff))[1];
        uint4 bl0 = ((const uint4*)(Bkl + boff))[0], bl1 = ((const uint4*)(Bkl + boff))[1];
        ((uint4*)(sAh + arow*40 + akq))[0] = ah0; ((uint4*)(sAh + arow*40 + akq))[1] = ah1;
        ((uint4*)(sAl + arow*40 + akq))[0] = al0; ((uint4*)(sAl + arow*40 + akq))[1] = al1;
        ((uint4*)(sBh + arow*40 + akq))[0] = bh0; ((uint4*)(sBh + arow*40 + akq))[1] = bh1;
        ((uint4*)(sBl + arow*40 + akq))[0] = bl0; ((uint4*)(sBl + arow*40 + akq))[1] = bl1;
        __syncthreads();
        #pragma unroll
        for (int kk = 0; kk < 32; kk += 16) {
            wmma::fragment<wmma::matrix_b, 16, 16, 16, bf16, wmma::col_major> fbh[2], fbl[2];
            #pragma unroll
            for (int j = 0; j < 2; j++) {
                wmma::load_matrix_sync(fbh[j], &sBh[(wn*32 + j*16)*40 + kk], 40);
                wmma::load_matrix_sync(fbl[j], &sBl[(wn*32 + j*16)*40 + kk], 40);
            }
            #pragma unroll
            for (int i = 0; i < 4; i++) {
                wmma::fragment<wmma::matrix_a, 16, 16, 16, bf16, wmma::row_major> fah, fal;
                wmma::load_matrix_sync(fah, &sAh[(wm*64 + i*16)*40 + kk], 40);
                wmma::load_matrix_sync(fal, &sAl[(wm*64 + i*16)*40 + kk], 40);
                #pragma unroll
                for (int j = 0; j < 2; j++) {
                    wmma::mma_sync(acc[i][j], fah, fbh[j], acc[i][j]);
                    wmma::mma_sync(acc[i][j], fah, fbl[j], acc[i][j]);
                    wmma::mma_sync(acc[i][j], fal, fbh[j], acc[i][j]);
                }
            }
        }
        __syncthreads();
    }
    const float scale = 0.0883883476483184f;
    #pragma unroll
    for (int i = 0; i < 4; i++)
        #pragma unroll
        for (int j = 0; j < 2; j++) {
            #pragma unroll
            for (int e = 0; e < acc[i][j].num_elements; e++) acc[i][j].x[e] *= scale;
            wmma::store_matrix_sync(&Cp[(size_t)(m0 + wm*64 + i*16)*S_ + n0 + wn*32 + j*16],
                                    acc[i][j], S_, wmma::mem_row_major);
        }
}

// ================== comb = sum_src (weighted P) @ V, plane in/out (R6) ============
__global__ void __launch_bounds__(256) comb_wmma(
    int nsrc,
    const bf16* __restrict__ Ph, const bf16* __restrict__ Pl,
    const bf16* __restrict__ Vh, const bf16* __restrict__ Vl,
    bf16* __restrict__ Ch, bf16* __restrict__ Cl)
{
    __shared__ __align__(16) char smraw[37888];
    bf16* sAh = (bf16*)(smraw);
    bf16* sAl = (bf16*)(smraw + 10240);
    bf16* sBh = (bf16*)(smraw + 20480);
    bf16* sBl = (bf16*)(smraw + 29184);
    float* stage = (float*)smraw;

    int bh = blockIdx.z, b = bh >> 3, h = bh & 7;
    int tid = threadIdx.x;
    int warp = tid >> 5;
    int wm = warp >> 2, wn = warp & 3;
    int m0 = blockIdx.y << 7;

    wmma::fragment<wmma::accumulator, 16, 16, 16, float> acc[4][2];
    #pragma unroll
    for (int i = 0; i < 4; i++)
        #pragma unroll
        for (int j = 0; j < 2; j++)
            wmma::fill_fragment(acc[i][j], 0.0f);

    int arow = tid >> 1, akq = (tid & 1) << 4;
    int bkr = tid >> 3, bnq = (tid & 7) << 4;

    for (int src = 0; src < nsrc; src++) {
        const bf16* Ah0 = Ph + ((size_t)src*16 + bh)*S_*S_;
        const bf16* Al0 = Pl + ((size_t)src*16 + bh)*S_*S_;
        const bf16* Bh0 = Vh + (size_t)src*SBD_ + bh*HD_;
        const bf16* Bl0 = Vl + (size_t)src*SBD_ + bh*HD_;
        for (int k0 = 0; k0 < S_; k0 += 32) {
            size_t aoff = (size_t)(m0 + arow)*S_ + k0 + akq;
            size_t boff = (size_t)(k0 + bkr)*(B_*D_) + bnq;
            uint4 ah0 = ((const uint4*)(Ah0 + aoff))[0], ah1 = ((const uint4*)(Ah0 + aoff))[1];
            uint4 al0 = ((const uint4*)(Al0 + aoff))[0], al1 = ((const uint4*)(Al0 + aoff))[1];
            uint4 bh0 = ((const uint4*)(Bh0 + boff))[0], bh1 = ((const uint4*)(Bh0 + boff))[1];
            uint4 bl0 = ((const uint4*)(Bl0 + boff))[0], bl1 = ((const uint4*)(Bl0 + boff))[1];
            ((uint4*)(sAh + arow*40 + akq))[0] = ah0; ((uint4*)(sAh + arow*40 + akq))[1] = ah1;
            ((uint4*)(sAl + arow*40 + akq))[0] = al0; ((uint4*)(sAl + arow*40 + akq))[1] = al1;
            ((uint4*)(sBh + bkr*136 + bnq))[0] = bh0; ((uint4*)(sBh + bkr*136 + bnq))[1] = bh1;
            ((uint4*)(sBl + bkr*136 + bnq))[0] = bl0; ((uint4*)(sBl + bkr*136 + bnq))[1] = bl1;
            __syncthreads();
            #pragma unroll
            for (int kk = 0; kk < 32; kk += 16) {
                wmma::fragment<wmma::matrix_b, 16, 16, 16, bf16, wmma::row_major> fbh[2], fbl[2];
                #pragma unroll
                for (int j = 0; j < 2; j++) {
                    wmma::load_matrix_sync(fbh[j], &sBh[kk*136 + wn*32 + j*16], 136);
                    wmma::load_matrix_sync(fbl[j], &sBl[kk*136 + wn*32 + j*16], 136);
                }
                #pragma unroll
                for (int i = 0; i < 4; i++) {
                    wmma::fragment<wmma::matrix_a, 16, 16, 16, bf16, wmma::row_major> fah, fal;
                    wmma::load_matrix_sync(fah, &sAh[(wm*64 + i*16)*40 + kk], 40);
                    wmma::load_matrix_sync(fal, &sAl[(wm*64 + i*16)*40 + kk], 40);
                    #pragma unroll
                    for (int j = 0; j < 2; j++) {
                        wmma::mma_sync(acc[i][j], fah, fbh[j], acc[i][j]);
                        wmma::mma_sync(acc[i][j], fah, fbl[j], acc[i][j]);
                        wmma::mma_sync(acc[i][j], fal, fbh[j], acc[i][j]);
                    }
                }
            }
            __syncthreads();
        }
    }

    #pragma unroll
    for (int ph = 0; ph < 2; ph++) {
        if (wm == ph) {
            #pragma unroll
            for (int i = 0; i < 4; i++)
                #pragma unroll
                for (int j = 0; j < 2; j++)
                    wmma::store_matrix_sync(&stage[(i*16)*132 + wn*32 + j*16],
                                            acc[i][j], 132, wmma::mem_row_major);
        }
        __syncthreads();
        int r = tid >> 2;
        int c0 = (tid & 3) << 5;
        int qrow = m0 + ph*64 + r;
        size_t base = ((size_t)qrow*B_ + b)*D_ + h*HD_ + c0;
        const float* srow = stage + r*132 + c0;
        #pragma unroll
        for (int g = 0; g < 8; g++) {
            float4 v = *(const float4*)(srow + g*4);
            cvt_store4(v, Ch + base + g*4, Cl + base + g*4);
        }
        __syncthreads();
    }
}

// ---------------- softmax over keys + layer weight -> bf16 planes -----------------
__global__ void __launch_bounds__(256) softmax_kernel(const float* __restrict__ P,
                                                      bf16* __restrict__ Ph,
                                                      bf16* __restrict__ Pl,
                                                      const float* __restrict__ dwl)
{
    int r = blockIdx.x*8 + (threadIdx.x >> 5);
    int lane = threadIdx.x & 31;
    const float* row = P + (size_t)r*256;
    float w = dwl[r >> 12];
    float v[8];
    #pragma unroll
    for (int i = 0; i < 8; i++) v[i] = row[lane*8 + i];
    float mx = v[0];
    #pragma unroll
    for (int i = 1; i < 8; i++) mx = fmaxf(mx, v[i]);
    #pragma unroll
    for (int o = 16; o; o >>= 1) mx = fmaxf(mx, __shfl_xor_sync(0xffffffffu, mx, o));
    float s = 0.f;
    #pragma unroll
    for (int i = 0; i < 8; i++) { v[i] = expf(v[i] - mx); s += v[i]; }
    #pragma unroll
    for (int o = 16; o; o >>= 1) s += __shfl_xor_sync(0xffffffffu, s, o);
    float sc = w / s;
    size_t base = (size_t)r*256 + lane*8;
    #pragma unroll
    for (int i = 0; i < 8; i += 4) {
        float4 q;
        q.x = v[i]*sc; q.y = v[i+1]*sc; q.z = v[i+2]*sc; q.w = v[i+3]*sc;
        cvt_store4(q, Ph + base + i, Pl + base + i);
    }
}

// ---------------- embedding + positional encoding -> fp32 + planes ----------------
__global__ void __launch_bounds__(256) embed_kernel(const int* __restrict__ src,
                                                    const float* __restrict__ emb,
                                                    float* __restrict__ X,
                                                    bf16* __restrict__ Xh,
                                                    bf16* __restrict__ Xl)
{
    int row = blockIdx.x;
    int s = row >> 1, b = row & 1;
    int tok = src[b*S_ + s];
    const float* e = emb + (size_t)tok*D_;
    size_t rb = (size_t)row*D_;
    const float c = -9.210340371976184f / (float)D_;
    #pragma unroll
    for (int i = 0; i < 4; i++) {
        int d = threadIdx.x + (i << 8);
        int ev = d & ~1;
        float div = expf((float)ev * c);
        float arg = (float)s * div;
        float pe = (d & 1) ? cosf(arg) : sinf(arg);
        float x = e[d]*32.0f + pe;
        X[rb + d] = x;
        cvt_store1(x, &Xh[rb + d], &Xl[rb + d]);
    }
}

// ---------------- distinct-source layer weights ----------------------------------
__global__ void dw_kernel(const float* __restrict__ lw, float* __restrict__ dw)
{
    int l = threadIdx.x;
    if (l >= L_) return;
    int n = l + 1;
    float w[17];
    float mx = -1e30f;
    for (int j = 0; j < n; j++) { w[j] = lw[l*(L_+1) + j]; mx = fmaxf(mx, w[j]); }
    float s = 0.f;
    for (int j = 0; j < n; j++) { w[j] = expf(w[j] - mx); s += w[j]; }
    for (int j = 0; j < n; j++) w[j] /= s;
    if (l == 0) dw[0] = w[0];
    else for (int j = 0; j < l; j++) dw[l*16 + j] = w[j+1] + ((j == l-1) ? w[0] : 0.f);
}

// ---------------- residual add + LayerNorm -> fp32 + planes -----------------------
__global__ void __launch_bounds__(256) addln_kernel(const float* __restrict__ x,
                                                    const float* __restrict__ r,
                                                    const float* __restrict__ g,
                                                    const float* __restrict__ be,
                                                    float* __restrict__ outf,
                                                    bf16* __restrict__ outh,
                                                    bf16* __restrict__ outl)
{
    int row = blockIdx.x;
    const float* xr = x + (size_t)row*D_;
    const float* rr = r + (size_t)row*D_;
    int lane = threadIdx.x & 31, wid = threadIdx.x >> 5;
    float v[4];
    float s = 0.f, sq = 0.f;
    #pragma unroll
    for (int i = 0; i < 4; i++) {
        int d = threadIdx.x + (i << 8);
        float a = xr[d] + rr[d];
        v[i] = a; s += a; sq += a*a;
    }
    #pragma unroll
    for (int o = 16; o; o >>= 1) {
        s  += __shfl_xor_sync(0xffffffffu, s, o);
        sq += __shfl_xor_sync(0xffffffffu, sq, o);
    }
    __shared__ float shs[8], shq[8], mv[2];
    if (lane == 0) { shs[wid] = s; shq[wid] = sq; }
    __syncthreads();
    if (wid == 0) {
        float a = (lane < 8) ? shs[lane] : 0.f;
        float bsum = (lane < 8) ? shq[lane] : 0.f;
        #pragma unroll
        for (int o = 4; o; o >>= 1) {
            a += __shfl_xor_sync(0xffffffffu, a, o);
            bsum += __shfl_xor_sync(0xffffffffu, bsum, o);
        }
        if (lane == 0) {
            float mean = a * (1.f/ (float)D_);
            float var  = bsum * (1.f/ (float)D_) - mean*mean;
            mv[0] = mean; mv[1] = rsqrtf(var + 1e-5f);
        }
    }
    __syncthreads();
    float mean = mv[0], rstd = mv[1];
    size_t rb = (size_t)row*D_;
    #pragma unroll
    for (int i = 0; i < 4; i++) {
        int d = threadIdx.x + (i << 8);
        float o = (v[i] - mean)*rstd*g[d] + be[d];
        outf[rb + d] = o;
        cvt_store1(o, &outh[rb + d], &outl[rb + d]);
    }
}

// ---------------- SNN scan (block version) -> bf16 spikes -------------------------
__global__ void __launch_bounds__(256) snn_kernel(const float* __restrict__ cur,
                                                  bf16* __restrict__ spikes)
{
    int b = blockIdx.x;
    int lane = threadIdx.x & 31, wid = threadIdx.x >> 5;
    float mem[4] = {0.f,0.f,0.f,0.f};
    float thr[4] = {1.f,1.f,1.f,1.f};
    __shared__ float sh[8];
    __shared__ float tot[2];
    for (int t = 0; t < S_; t++) {
        float p = mem[0]+mem[1]+mem[2]+mem[3];
        #pragma unroll
        for (int o = 16; o; o >>= 1) p += __shfl_xor_sync(0xffffffffu, p, o);
        if (lane == 0) sh[wid] = p;
        __syncthreads();
        if (wid == 0) {
            float v = (lane < 8) ? sh[lane] : 0.f;
            #pragma unroll
            for (int o = 4; o; o >>= 1) v += __shfl_xor_sync(0xffffffffu, v, o);
            if (lane == 0) tot[t & 1] = v;
        }
        __syncthreads();
        float M = tot[t & 1];
        const float* cr = cur    + ((size_t)t*B_ + b)*D_;
        bf16*        sr = spikes + ((size_t)t*B_ + b)*D_;
        #pragma unroll
        for (int i = 0; i < 4; i++) {
            int d = threadIdx.x + (i << 8);
            float c  = cr[d] - 0.1f*M;
            float m2 = 0.9f*mem[i] + c;
            float sp = (m2 >= thr[i]) ? 1.f : 0.f;
            mem[i] = m2 - sp*thr[i];
            thr[i] = 0.9f*thr[i] + 0.1f*sp;
            sr[d] = __float2bfloat16(sp);
        }
    }
}

// ---------------- host orchestration ---------------------------------------------
extern "C" void kernel_launch(void* const* d_in, const int* in_sizes, int n_in,
                              void* d_out, int out_size)
{
    const int*   src  = (const int*)  d_in[0];
    const float* emb  = (const float*)d_in[1];
    const float* Wq   = (const float*)d_in[2];
    const float* bq   = (const float*)d_in[3];
    const float* Wk   = (const float*)d_in[4];
    const float* bk   = (const float*)d_in[5];
    const float* Wv   = (const float*)d_in[6];
    const float* bv   = (const float*)d_in[7];
    const float* Wo   = (const float*)d_in[8];
    const float* bo   = (const float*)d_in[9];
    const float* lw   = (const float*)d_in[10];
    const float* Wsnn = (const float*)d_in[11];
    const float* bsnn = (const float*)d_in[12];
    const float* W1   = (const float*)d_in[13];
    const float* b1   = (const float*)d_in[14];
    const float* W2   = (const float*)d_in[15];
    const float* b2   = (const float*)d_in[16];
    const float* g1   = (const float*)d_in[17];
    const float* be1  = (const float*)d_in[18];
    const float* g2   = (const float*)d_in[19];
    const float* be2  = (const float*)d_in[20];
    const float* Wout = (const float*)d_in[21];
    const float* bout = (const float*)d_in[22];
    float* out = (float*)d_out;

    float *x0,*lo,*sc,*xa,*t2,*dw;
    cudaGetSymbolAddress((void**)&x0, g_x0);
    cudaGetSymbolAddress((void**)&lo, g_lo);
    cudaGetSymbolAddress((void**)&sc, g_sc);
    cudaGetSymbolAddress((void**)&xa, g_xa);
    cudaGetSymbolAddress((void**)&t2, g_t2);
    cudaGetSymbolAddress((void**)&dw, g_dw);

    bf16 *x0h,*x0l,*loh,*lol,*qh,*ql,*kh,*kl,*vh,*vl,*sch,*scl,*combh,*combl,*xah,*xal,*sph,*tffh,*tffl;
    cudaGetSymbolAddress((void**)&x0h, g_x0h);   cudaGetSymbolAddress((void**)&x0l, g_x0l);
    cudaGetSymbolAddress((void**)&loh, g_loh);   cudaGetSymbolAddress((void**)&lol, g_lol);
    cudaGetSymbolAddress((void**)&qh,  g_qh);    cudaGetSymbolAddress((void**)&ql,  g_ql);
    cudaGetSymbolAddress((void**)&kh,  g_kh);    cudaGetSymbolAddress((void**)&kl,  g_kl);
    cudaGetSymbolAddress((void**)&vh,  g_vh);    cudaGetSymbolAddress((void**)&vl,  g_vl);
    cudaGetSymbolAddress((void**)&sch, g_sch);   cudaGetSymbolAddress((void**)&scl, g_scl);
    cudaGetSymbolAddress((void**)&combh, g_combh); cudaGetSymbolAddress((void**)&combl, g_combl);
    cudaGetSymbolAddress((void**)&xah, g_xah);   cudaGetSymbolAddress((void**)&xal, g_xal);
    cudaGetSymbolAddress((void**)&sph, g_sph);
    cudaGetSymbolAddress((void**)&tffh, g_tffh); cudaGetSymbolAddress((void**)&tffl, g_tffl);

    bf16 *wqh,*wql,*wkh,*wkl,*wvh,*wvl,*woh,*wol,*wsh,*wsl,*w1h,*w1l,*w2h,*w2l,*wouth,*woutl;
    cudaGetSymbolAddress((void**)&wqh, g_wqh);   cudaGetSymbolAddress((void**)&wql, g_wql);
    cudaGetSymbolAddress((void**)&wkh, g_wkh);   cudaGetSymbolAddress((void**)&wkl, g_wkl);
    cudaGetSymbolAddress((void**)&wvh, g_wvh);   cudaGetSymbolAddress((void**)&wvl, g_wvl);
    cudaGetSymbolAddress((void**)&woh, g_woh);   cudaGetSymbolAddress((void**)&wol, g_wol);
    cudaGetSymbolAddress((void**)&wsh, g_wsh);   cudaGetSymbolAddress((void**)&wsl, g_wsl);
    cudaGetSymbolAddress((void**)&w1h, g_w1h);   cudaGetSymbolAddress((void**)&w1l, g_w1l);
    cudaGetSymbolAddress((void**)&w2h, g_w2h);   cudaGetSymbolAddress((void**)&w2l, g_w2l);
    cudaGetSymbolAddress((void**)&wouth, g_wouth); cudaGetSymbolAddress((void**)&woutl, g_woutl);

    // ---- weight pre-split (memory-bound) ----
    const int NW = L_*D_*D_;
    const int NF = L_*D_*FF_;
    cvtw_kernel<<<NW/1024, 256>>>(Wq, wqh, wql, NW);
    cvtw_kernel<<<NW/1024, 256>>>(Wk, wkh, wkl, NW);
    cvtw_kernel<<<NW/1024, 256>>>(Wv, wvh, wvl, NW);
    cvtw_kernel<<<NW/1024, 256>>>(Wo, woh, wol, NW);
    cvtw_kernel<<<NW/1024, 256>>>(Wsnn, wsh, wsl, NW);
    cvtw_kernel<<<NF/1024, 256>>>(W1, w1h, w1l, NF);
    cvtw_kernel<<<NF/1024, 256>>>(W2, w2h, w2l, NF);
    cvtwout_kernel<<<dim3(NPV_/256, D_), 256>>>(Wout, wouth, woutl);

    embed_kernel<<<SB_, 256>>>(src, emb, x0, x0h, x0l);
    dw_kernel<<<1, 32>>>(lw, dw);

    for (int l = 0; l < L_; l++) {
        int nsrc = (l == 0) ? 1 : l;
        const bf16* sbh = (l == 0) ? x0h : loh;
        const bf16* sbl = (l == 0) ? x0l : lol;
        const bf16* xinh = (l == 0) ? x0h : (loh + (size_t)(l-1)*SBD_);
        const bf16* xinl = (l == 0) ? x0l : (lol + (size_t)(l-1)*SBD_);
        const float* xinf = (l == 0) ? x0 : (lo + (size_t)(l-1)*SBD_);

        // merged K+V projection (one launch), then Q
        kv_wmma<<<dim3(16, nsrc*4), 256>>>(
            sbh, sbl,
            wkh + (size_t)l*D_*D_, wkl + (size_t)l*D_*D_,
            wvh + (size_t)l*D_*D_, wvl + (size_t)l*D_*D_,
            bk + l*D_, bv + l*D_,
            kh, kl, vh, vl);
        gemm_wmma<1,false,false,false><<<dim3(D_/128, SB_/128), 256>>>(
            D_, D_, xinh, xinl, D_, wqh + (size_t)l*D_*D_, wql + (size_t)l*D_*D_, D_,
            bq + l*D_, nullptr, qh, ql, D_);

        qk_wmma<<<dim3(2, 2, nsrc*16), 256>>>(qh, ql, kh, kl, sc);
        softmax_kernel<<<nsrc*512, 256>>>(sc, sch, scl, dw + l*16);
        comb_wmma<<<dim3(1, 2, 16), 256>>>(nsrc, sch, scl, vh, vl, combh, combl);

        // Wo projection -> fp32, then add+LN -> xa fp32 + planes
        gemm_wmma<0,false,false,false><<<dim3(D_/128, SB_/128), 256>>>(
            D_, D_, combh, combl, D_, woh + (size_t)l*D_*D_, wol + (size_t)l*D_*D_, D_,
            bo + l*D_, t2, nullptr, nullptr, D_);
        addln_kernel<<<SB_, 256>>>(xinf, t2, g1 + l*D_, be1 + l*D_, xa, xah, xal);

        // SNN projection -> fp32, scan -> bf16 spikes
        gemm_wmma<0,false,false,false><<<dim3(D_/128, SB_/128), 256>>>(
            D_, D_, xah, xal, D_, wsh + (size_t)l*D_*D_, wsl + (size_t)l*D_*D_, D_,
            bsnn + l*D_, t2, nullptr, nullptr, D_);
        snn_kernel<<<B_, 256>>>(t2, sph);

        // FFN: FF1 (A exact bf16, ReLU) -> planes; FF2 -> fp32; add+LN -> lo[l]
        gemm_wmma<1,true,false,true><<<dim3(FF_/128, SB_/128), 256>>>(
            FF_, D_, sph, sph, D_, w1h + (size_t)l*D_*FF_, w1l + (size_t)l*D_*FF_, FF_,
            b1 + l*FF_, nullptr, tffh, tffl, FF_);
        gemm_wmma<0,false,false,false><<<dim3(D_/128, SB_/128), 256>>>(
            D_, FF_, tffh, tffl, FF_, w2h + (size_t)l*FF_*D_, w2l + (size_t)l*FF_*D_, D_,
            b2 + l*D_, t2, nullptr, nullptr, D_);
        addln_kernel<<<SB_, 256>>>(xa, t2, g2 + l*D_, be2 + l*D_,
                                   lo + (size_t)l*SBD_,
                                   loh + (size_t)l*SBD_, lol + (size_t)l*SBD_);
    }

    // final vocab projection (fp32 out, fused [S,B]->[B,S] transpose)
    gemm_wmma<0,false,true,false><<<dim3((V_+127)/128, SB_/128), 256>>>(
        V_, D_, loh + (size_t)15*SBD_, lol + (size_t)15*SBD_, D_,
        wouth, woutl, NPV_, bout, out, nullptr, nullptr, V_);
}

// round 14
// speedup vs baseline: 1.6642x; 1.6642x over previous
#include <cuda_runtime.h>
#include <cuda_bf16.h>
#include <mma.h>
#include <math.h>

using namespace nvcuda;

#define B_   2
#define S_   256
#define D_   1024
#define H_   8
#define L_   16
#define FF_  2048
#define V_   50257
#define NPV_ 50432
#define HD_  128
#define SB_  (S_*B_)          // 512
#define SBD_ (SB_*D_)         // 524288

typedef __nv_bfloat16 bf16;

// ---------------- fp32 masters ----------------------------------------------------
static __device__ float g_x0[SBD_];
static __device__ float g_lo[L_*SBD_];
static __device__ float g_sc[15*16*S_*S_];
static __device__ float g_xa[SBD_];
static __device__ float g_t2[2*SBD_];       // split-K partial pair
static __device__ float g_cmbf[SBD_];       // comb fp32 accumulator
static __device__ float g_dw[L_*16];
static __device__ float g_zero[1024];       // zero bias for split-K half 1

// ---------------- bf16 hi/lo activation planes ------------------------------------
static __device__ __align__(16) bf16 g_x0h[SBD_],  g_x0l[SBD_];
static __device__ __align__(16) bf16 g_loh[L_*SBD_], g_lol[L_*SBD_];
static __device__ __align__(16) bf16 g_qh[SBD_],   g_ql[SBD_];
static __device__ __align__(16) bf16 g_kh[15*SBD_], g_kl[15*SBD_];
static __device__ __align__(16) bf16 g_vh[15*SBD_], g_vl[15*SBD_];
static __device__ __align__(16) bf16 g_sch[15*16*S_*S_], g_scl[15*16*S_*S_];
static __device__ __align__(16) bf16 g_combh[SBD_], g_combl[SBD_];
static __device__ __align__(16) bf16 g_xah[SBD_],  g_xal[SBD_];
static __device__ __align__(16) bf16 g_sph[SBD_];
static __device__ __align__(16) bf16 g_tffh[SB_*FF_], g_tffl[SB_*FF_];

// ---------------- bf16 hi/lo weight planes ----------------------------------------
static __device__ __align__(16) bf16 g_wqh[L_*D_*D_],  g_wql[L_*D_*D_];
static __device__ __align__(16) bf16 g_wkh[L_*D_*D_],  g_wkl[L_*D_*D_];
static __device__ __align__(16) bf16 g_wvh[L_*D_*D_],  g_wvl[L_*D_*D_];
static __device__ __align__(16) bf16 g_woh[L_*D_*D_],  g_wol[L_*D_*D_];
static __device__ __align__(16) bf16 g_wsh[L_*D_*D_],  g_wsl[L_*D_*D_];
static __device__ __align__(16) bf16 g_w1h[L_*D_*FF_], g_w1l[L_*D_*FF_];
static __device__ __align__(16) bf16 g_w2h[L_*FF_*D_], g_w2l[L_*FF_*D_];
static __device__ __align__(16) bf16 g_wouth[D_*NPV_], g_woutl[D_*NPV_];

// ================== split helpers =================================================
__device__ __forceinline__ void cvt_store4(float4 v, bf16* hp, bf16* lp)
{
    bf16 h0 = __float2bfloat16(v.x), h1 = __float2bfloat16(v.y);
    bf16 h2 = __float2bfloat16(v.z), h3 = __float2bfloat16(v.w);
    bf16 l0 = __float2bfloat16(v.x - __bfloat162float(h0));
    bf16 l1 = __float2bfloat16(v.y - __bfloat162float(h1));
    bf16 l2 = __float2bfloat16(v.z - __bfloat162float(h2));
    bf16 l3 = __float2bfloat16(v.w - __bfloat162float(h3));
    __nv_bfloat162 a; a.x = h0; a.y = h1;
    __nv_bfloat162 b; b.x = h2; b.y = h3;
    __nv_bfloat162 c; c.x = l0; c.y = l1;
    __nv_bfloat162 d; d.x = l2; d.y = l3;
    *(__nv_bfloat162*)(hp)   = a;  *(__nv_bfloat162*)(hp+2) = b;
    *(__nv_bfloat162*)(lp)   = c;  *(__nv_bfloat162*)(lp+2) = d;
}
__device__ __forceinline__ void cvt_store1(float x, bf16* hp, bf16* lp)
{
    bf16 h = __float2bfloat16(x);
    *hp = h;
    *lp = __float2bfloat16(x - __bfloat162float(h));
}

// ================== weight / buffer conversion ====================================
__global__ void __launch_bounds__(256) cvtw_kernel(const float* __restrict__ src,
                                                   bf16* __restrict__ h,
                                                   bf16* __restrict__ l, int n)
{
    int i = (blockIdx.x*256 + threadIdx.x)*4;
    if (i >= n) return;
    float4 v = *(const float4*)(src + i);
    cvt_store4(v, h + i, l + i);
}
__global__ void __launch_bounds__(256) cvtwout_kernel(const float* __restrict__ src,
                                                      bf16* __restrict__ h,
                                                      bf16* __restrict__ l)
{
    int n = blockIdx.x*256 + threadIdx.x;
    int row = blockIdx.y;
    float x = (n < V_) ? src[(size_t)row*V_ + n] : 0.f;
    cvt_store1(x, &h[(size_t)row*NPV_ + n], &l[(size_t)row*NPV_ + n]);
}

// ================== GEMM core (R6 body, static smem) ==============================
template<int OM, bool RELU, bool OUTBS, bool AEX>
__device__ __forceinline__ void gemm_core(
    int N, int K,
    const bf16* __restrict__ Ahg, const bf16* __restrict__ Alg, int lda,
    const bf16* __restrict__ Bhg, const bf16* __restrict__ Blg, int ldb,
    const float* __restrict__ bias,
    float* __restrict__ Cf, bf16* __restrict__ Ch, bf16* __restrict__ Cl, int ldc,
    int m0, int n0, char* smraw)
{
    bf16* sAh = (bf16*)(smraw);
    bf16* sAl = (bf16*)(smraw + 10240);
    bf16* sBh = (bf16*)(smraw + 20480);
    bf16* sBl = (bf16*)(smraw + 29184);
    float* stage = (float*)smraw;

    int tid = threadIdx.x;
    int warp = tid >> 5;
    int wm = warp >> 2, wn = warp & 3;

    wmma::fragment<wmma::accumulator, 16, 16, 16, float> acc[4][2];
    #pragma unroll
    for (int i = 0; i < 4; i++)
        #pragma unroll
        for (int j = 0; j < 2; j++)
            wmma::fill_fragment(acc[i][j], 0.0f);

    int arow = tid >> 1, akq = (tid & 1) << 4;
    int bkr = tid >> 3, bnq = (tid & 7) << 4;

    const bf16* Ah0 = Ahg + (size_t)(m0 + arow)*lda + akq;
    const bf16* Al0 = AEX ? Ah0 : (Alg + (size_t)(m0 + arow)*lda + akq);

    for (int k0 = 0; k0 < K; k0 += 32) {
        {
            const uint4* ph = (const uint4*)(Ah0 + k0);
            uint4 h0 = ph[0], h1 = ph[1];
            ((uint4*)(sAh + arow*40 + akq))[0] = h0;
            ((uint4*)(sAh + arow*40 + akq))[1] = h1;
            if (!AEX) {
                const uint4* pl = (const uint4*)(Al0 + k0);
                uint4 l0 = pl[0], l1 = pl[1];
                ((uint4*)(sAl + arow*40 + akq))[0] = l0;
                ((uint4*)(sAl + arow*40 + akq))[1] = l1;
            }
        }
        {
            const uint4* ph = (const uint4*)(Bhg + (size_t)(k0 + bkr)*ldb + n0 + bnq);
            const uint4* pl = (const uint4*)(Blg + (size_t)(k0 + bkr)*ldb + n0 + bnq);
            uint4 h0 = ph[0], h1 = ph[1];
            uint4 l0 = pl[0], l1 = pl[1];
            ((uint4*)(sBh + bkr*136 + bnq))[0] = h0;
            ((uint4*)(sBh + bkr*136 + bnq))[1] = h1;
            ((uint4*)(sBl + bkr*136 + bnq))[0] = l0;
            ((uint4*)(sBl + bkr*136 + bnq))[1] = l1;
        }
        __syncthreads();
        #pragma unroll
        for (int kk = 0; kk < 32; kk += 16) {
            wmma::fragment<wmma::matrix_b, 16, 16, 16, bf16, wmma::row_major> fbh[2], fbl[2];
            #pragma unroll
            for (int j = 0; j < 2; j++) {
                wmma::load_matrix_sync(fbh[j], &sBh[kk*136 + wn*32 + j*16], 136);
                wmma::load_matrix_sync(fbl[j], &sBl[kk*136 + wn*32 + j*16], 136);
            }
            #pragma unroll
            for (int i = 0; i < 4; i++) {
                wmma::fragment<wmma::matrix_a, 16, 16, 16, bf16, wmma::row_major> fah, fal;
                wmma::load_matrix_sync(fah, &sAh[(wm*64 + i*16)*40 + kk], 40);
                if (!AEX) wmma::load_matrix_sync(fal, &sAl[(wm*64 + i*16)*40 + kk], 40);
                #pragma unroll
                for (int j = 0; j < 2; j++) {
                    wmma::mma_sync(acc[i][j], fah, fbh[j], acc[i][j]);
                    wmma::mma_sync(acc[i][j], fah, fbl[j], acc[i][j]);
                    if (!AEX) wmma::mma_sync(acc[i][j], fal, fbh[j], acc[i][j]);
                }
            }
        }
        __syncthreads();
    }

    const bool valigned = ((ldc & 3) == 0);
    #pragma unroll
    for (int ph = 0; ph < 2; ph++) {
        if (wm == ph) {
            #pragma unroll
            for (int i = 0; i < 4; i++)
                #pragma unroll
                for (int j = 0; j < 2; j++)
                    wmma::store_matrix_sync(&stage[(i*16)*132 + wn*32 + j*16],
                                            acc[i][j], 132, wmma::mem_row_major);
        }
        __syncthreads();
        int r = tid >> 2;
        int c0 = (tid & 3) << 5;
        int m = m0 + ph*64 + r;
        int orow = OUTBS ? ((m & 1)*S_ + (m >> 1)) : m;
        const float* srow = stage + r*132 + c0;
        int nb = n0 + c0;
        if (OM == 1) {
            bf16* hrow = Ch + (size_t)orow*ldc;
            bf16* lrow = Cl + (size_t)orow*ldc;
            #pragma unroll
            for (int g = 0; g < 8; g++) {
                float4 v = *(const float4*)(srow + g*4);
                float4 bb = *(const float4*)(bias + nb + g*4);
                v.x += bb.x; v.y += bb.y; v.z += bb.z; v.w += bb.w;
                if (RELU) {
                    v.x = fmaxf(v.x, 0.f); v.y = fmaxf(v.y, 0.f);
                    v.z = fmaxf(v.z, 0.f); v.w = fmaxf(v.w, 0.f);
                }
                cvt_store4(v, hrow + nb + g*4, lrow + nb + g*4);
            }
        } else {
            float* crow = Cf + (size_t)orow*ldc;
            if (valigned && nb + 32 <= N) {
                #pragma unroll
                for (int g = 0; g < 8; g++) {
                    float4 v = *(const float4*)(srow + g*4);
                    float4 bb = *(const float4*)(bias + nb + g*4);
                    v.x += bb.x; v.y += bb.y; v.z += bb.z; v.w += bb.w;
                    if (RELU) {
                        v.x = fmaxf(v.x, 0.f); v.y = fmaxf(v.y, 0.f);
                        v.z = fmaxf(v.z, 0.f); v.w = fmaxf(v.w, 0.f);
                    }
                    *(float4*)(crow + nb + g*4) = v;
                }
            } else {
                for (int g = 0; g < 32; g++) {
                    int n = nb + g;
                    if (n < N) {
                        float v = srow[g] + bias[n];
                        if (RELU) v = fmaxf(v, 0.f);
                        crow[n] = v;
                    }
                }
            }
        }
        __syncthreads();
    }
}

template<int OM, bool RELU, bool OUTBS, bool AEX>
__global__ void __launch_bounds__(256) gemm_wmma(
    int N, int K,
    const bf16* __restrict__ Ahg, const bf16* __restrict__ Alg, int lda,
    const bf16* __restrict__ Bhg, const bf16* __restrict__ Blg, int ldb,
    const float* __restrict__ bias,
    float* __restrict__ Cf, bf16* __restrict__ Ch, bf16* __restrict__ Cl, int ldc)
{
    __shared__ __align__(16) char smraw[37888];
    gemm_core<OM, RELU, OUTBS, AEX>(N, K, Ahg, Alg, lda, Bhg, Blg, ldb, bias,
                                    Cf, Ch, Cl, ldc,
                                    blockIdx.y << 7, blockIdx.x << 7, smraw);
}

// split-K=2 GEMM: z selects K half; partial into Cf + z*pstride, bias only on z=0.
__global__ void __launch_bounds__(256) gemm_wmma_sk(
    int N, int Khalf,
    const bf16* __restrict__ Ahg, const bf16* __restrict__ Alg, int lda,
    const bf16* __restrict__ Bhg, const bf16* __restrict__ Blg, int ldb,
    const float* __restrict__ bias,
    float* __restrict__ Cf, int ldc, int pstride)
{
    __shared__ __align__(16) char smraw[37888];
    int z = blockIdx.z;
    gemm_core<0, false, false, false>(N, Khalf,
        Ahg + z*Khalf, Alg + z*Khalf, lda,
        Bhg + (size_t)z*Khalf*ldb, Blg + (size_t)z*Khalf*ldb, ldb,
        z ? g_zero : bias,
        Cf + (size_t)z*pstride, nullptr, nullptr, ldc,
        blockIdx.y << 7, blockIdx.x << 7, smraw);
}

// ================== QK scores (NT, R6 body) =======================================
__global__ void __launch_bounds__(256) qk_wmma(
    const bf16* __restrict__ Qh, const bf16* __restrict__ Ql,
    const bf16* __restrict__ Kh, const bf16* __restrict__ Kl,
    float* __restrict__ P)
{
    __shared__ __align__(16) char smraw[40960];
    bf16* sAh = (bf16*)(smraw);
    bf16* sAl = (bf16*)(smraw + 10240);
    bf16* sBh = (bf16*)(smraw + 20480);
    bf16* sBl = (bf16*)(smraw + 30720);

    int z = blockIdx.z;
    int src = z >> 4, bh = z & 15;
    const bf16* Aqh = Qh + bh*HD_;
    const bf16* Aql = Ql + bh*HD_;
    const bf16* Bkh = Kh + (size_t)src*SBD_ + bh*HD_;
    const bf16* Bkl = Kl + (size_t)src*SBD_ + bh*HD_;
    float* Cp = P + (size_t)z*S_*S_;

    int tid = threadIdx.x;
    int warp = tid >> 5;
    int wm = warp >> 2, wn = warp & 3;
    int m0 = blockIdx.y << 7, n0 = blockIdx.x << 7;

    wmma::fragment<wmma::accumulator, 16, 16, 16, float> acc[4][2];
    #pragma unroll
    for (int i = 0; i < 4; i++)
        #pragma unroll
        for (int j = 0; j < 2; j++)
            wmma::fill_fragment(acc[i][j], 0.0f);

    int arow = tid >> 1, akq = (tid & 1) << 4;

    for (int k0 = 0; k0 < HD_; k0 += 32) {
        size_t aoff = (size_t)(m0 + arow)*(B_*D_) + k0 + akq;
        size_t boff = (size_t)(n0 + arow)*(B_*D_) + k0 + akq;
        uint4 ah0 = ((const uint4*)(Aqh + aoff))[0], ah1 = ((const uint4*)(Aqh + aoff))[1];
        uint4 al0 = ((const uint4*)(Aql + aoff))[0], al1 = ((const uint4*)(Aql + aoff))[1];
        uint4 bh0 = ((const uint4*)(Bkh + boff))[0], bh1 = ((const uint4*)(Bkh + boff))[1];
        uint4 bl0 = ((const uint4*)(Bkl + boff))[0], bl1 = ((const uint4*)(Bkl + boff))[1];
        ((uint4*)(sAh + arow*40 + akq))[0] = ah0; ((uint4*)(sAh + arow*40 + akq))[1] = ah1;
        ((uint4*)(sAl + arow*40 + akq))[0] = al0; ((uint4*)(sAl + arow*40 + akq))[1] = al1;
        ((uint4*)(sBh + arow*40 + akq))[0] = bh0; ((uint4*)(sBh + arow*40 + akq))[1] = bh1;
        ((uint4*)(sBl + arow*40 + akq))[0] = bl0; ((uint4*)(sBl + arow*40 + akq))[1] = bl1;
        __syncthreads();
        #pragma unroll
        for (int kk = 0; kk < 32; kk += 16) {
            wmma::fragment<wmma::matrix_b, 16, 16, 16, bf16, wmma::col_major> fbh[2], fbl[2];
            #pragma unroll
            for (int j = 0; j < 2; j++) {
                wmma::load_matrix_sync(fbh[j], &sBh[(wn*32 + j*16)*40 + kk], 40);
                wmma::load_matrix_sync(fbl[j], &sBl[(wn*32 + j*16)*40 + kk], 40);
            }
            #pragma unroll
            for (int i = 0; i < 4; i++) {
                wmma::fragment<wmma::matrix_a, 16, 16, 16, bf16, wmma::row_major> fah, fal;
                wmma::load_matrix_sync(fah, &sAh[(wm*64 + i*16)*40 + kk], 40);
                wmma::load_matrix_sync(fal, &sAl[(wm*64 + i*16)*40 + kk], 40);
                #pragma unroll
                for (int j = 0; j < 2; j++) {
                    wmma::mma_sync(acc[i][j], fah, fbh[j], acc[i][j]);
                    wmma::mma_sync(acc[i][j], fah, fbl[j], acc[i][j]);
                    wmma::mma_sync(acc[i][j], fal, fbh[j], acc[i][j]);
                }
            }
        }
        __syncthreads();
    }
    const float scale = 0.0883883476483184f;
    #pragma unroll
    for (int i = 0; i < 4; i++)
        #pragma unroll
        for (int j = 0; j < 2; j++) {
            #pragma unroll
            for (int e = 0; e < acc[i][j].num_elements; e++) acc[i][j].x[e] *= scale;
            wmma::store_matrix_sync(&Cp[(size_t)(m0 + wm*64 + i*16)*S_ + n0 + wn*32 + j*16],
                                    acc[i][j], S_, wmma::mem_row_major);
        }
}

// ================== comb: chunked sources, fp32 atomic accumulate =================
// grid (1, 2, 16*nchunk): chunk = z>>4 handles sources [chunk*4, min(+4, nsrc)).
__global__ void __launch_bounds__(256) comb_wmma(
    int nsrc,
    const bf16* __restrict__ Ph, const bf16* __restrict__ Pl,
    const bf16* __restrict__ Vh, const bf16* __restrict__ Vl,
    float* __restrict__ Cc)
{
    __shared__ __align__(16) char smraw[37888];
    bf16* sAh = (bf16*)(smraw);
    bf16* sAl = (bf16*)(smraw + 10240);
    bf16* sBh = (bf16*)(smraw + 20480);
    bf16* sBl = (bf16*)(smraw + 29184);
    float* stage = (float*)smraw;

    int bh = blockIdx.z & 15, chunk = blockIdx.z >> 4;
    int b = bh >> 3, h = bh & 7;
    int s0 = chunk*4;
    int send = s0 + 4; if (send > nsrc) send = nsrc;
    int tid = threadIdx.x;
    int warp = tid >> 5;
    int wm = warp >> 2, wn = warp & 3;
    int m0 = blockIdx.y << 7;

    wmma::fragment<wmma::accumulator, 16, 16, 16, float> acc[4][2];
    #pragma unroll
    for (int i = 0; i < 4; i++)
        #pragma unroll
        for (int j = 0; j < 2; j++)
            wmma::fill_fragment(acc[i][j], 0.0f);

    int arow = tid >> 1, akq = (tid & 1) << 4;
    int bkr = tid >> 3, bnq = (tid & 7) << 4;

    for (int src = s0; src < send; src++) {
        const bf16* Ah0 = Ph + ((size_t)src*16 + bh)*S_*S_;
        const bf16* Al0 = Pl + ((size_t)src*16 + bh)*S_*S_;
        const bf16* Bh0 = Vh + (size_t)src*SBD_ + bh*HD_;
        const bf16* Bl0 = Vl + (size_t)src*SBD_ + bh*HD_;
        for (int k0 = 0; k0 < S_; k0 += 32) {
            size_t aoff = (size_t)(m0 + arow)*S_ + k0 + akq;
            size_t boff = (size_t)(k0 + bkr)*(B_*D_) + bnq;
            uint4 ah0 = ((const uint4*)(Ah0 + aoff))[0], ah1 = ((const uint4*)(Ah0 + aoff))[1];
            uint4 al0 = ((const uint4*)(Al0 + aoff))[0], al1 = ((const uint4*)(Al0 + aoff))[1];
            uint4 bh0 = ((const uint4*)(Bh0 + boff))[0], bh1 = ((const uint4*)(Bh0 + boff))[1];
            uint4 bl0 = ((const uint4*)(Bl0 + boff))[0], bl1 = ((const uint4*)(Bl0 + boff))[1];
            ((uint4*)(sAh + arow*40 + akq))[0] = ah0; ((uint4*)(sAh + arow*40 + akq))[1] = ah1;
            ((uint4*)(sAl + arow*40 + akq))[0] = al0; ((uint4*)(sAl + arow*40 + akq))[1] = al1;
            ((uint4*)(sBh + bkr*136 + bnq))[0] = bh0; ((uint4*)(sBh + bkr*136 + bnq))[1] = bh1;
            ((uint4*)(sBl + bkr*136 + bnq))[0] = bl0; ((uint4*)(sBl + bkr*136 + bnq))[1] = bl1;
            __syncthreads();
            #pragma unroll
            for (int kk = 0; kk < 32; kk += 16) {
                wmma::fragment<wmma::matrix_b, 16, 16, 16, bf16, wmma::row_major> fbh[2], fbl[2];
                #pragma unroll
                for (int j = 0; j < 2; j++) {
                    wmma::load_matrix_sync(fbh[j], &sBh[kk*136 + wn*32 + j*16], 136);
                    wmma::load_matrix_sync(fbl[j], &sBl[kk*136 + wn*32 + j*16], 136);
                }
                #pragma unroll
                for (int i = 0; i < 4; i++) {
                    wmma::fragment<wmma::matrix_a, 16, 16, 16, bf16, wmma::row_major> fah, fal;
                    wmma::load_matrix_sync(fah, &sAh[(wm*64 + i*16)*40 + kk], 40);
                    wmma::load_matrix_sync(fal, &sAl[(wm*64 + i*16)*40 + kk], 40);
                    #pragma unroll
                    for (int j = 0; j < 2; j++) {
                        wmma::mma_sync(acc[i][j], fah, fbh[j], acc[i][j]);
                        wmma::mma_sync(acc[i][j], fah, fbl[j], acc[i][j]);
                        wmma::mma_sync(acc[i][j], fal, fbh[j], acc[i][j]);
                    }
                }
            }
            __syncthreads();
        }
    }

    // atomic fp32 epilogue into [S,B,D]
    #pragma unroll
    for (int ph = 0; ph < 2; ph++) {
        if (wm == ph) {
            #pragma unroll
            for (int i = 0; i < 4; i++)
                #pragma unroll
                for (int j = 0; j < 2; j++)
                    wmma::store_matrix_sync(&stage[(i*16)*132 + wn*32 + j*16],
                                            acc[i][j], 132, wmma::mem_row_major);
        }
        __syncthreads();
        int r = tid >> 2;
        int c0 = (tid & 3) << 5;
        int qrow = m0 + ph*64 + r;
        float* crow = Cc + ((size_t)qrow*B_ + b)*D_ + h*HD_;
        const float* srow = stage + r*132 + c0;
        #pragma unroll
        for (int g = 0; g < 32; g++)
            atomicAdd(&crow[c0 + g], srow[g]);
        __syncthreads();
    }
}

// ---------------- softmax over keys + layer weight -> bf16 planes -----------------
__global__ void __launch_bounds__(256) softmax_kernel(const float* __restrict__ P,
                                                      bf16* __restrict__ Ph,
                                                      bf16* __restrict__ Pl,
                                                      const float* __restrict__ dwl)
{
    int r = blockIdx.x*8 + (threadIdx.x >> 5);
    int lane = threadIdx.x & 31;
    const float* row = P + (size_t)r*256;
    float w = dwl[r >> 12];
    float v[8];
    #pragma unroll
    for (int i = 0; i < 8; i++) v[i] = row[lane*8 + i];
    float mx = v[0];
    #pragma unroll
    for (int i = 1; i < 8; i++) mx = fmaxf(mx, v[i]);
    #pragma unroll
    for (int o = 16; o; o >>= 1) mx = fmaxf(mx, __shfl_xor_sync(0xffffffffu, mx, o));
    float s = 0.f;
    #pragma unroll
    for (int i = 0; i < 8; i++) { v[i] = expf(v[i] - mx); s += v[i]; }
    #pragma unroll
    for (int o = 16; o; o >>= 1) s += __shfl_xor_sync(0xffffffffu, s, o);
    float sc = w / s;
    size_t base = (size_t)r*256 + lane*8;
    #pragma unroll
    for (int i = 0; i < 8; i += 4) {
        float4 q;
        q.x = v[i]*sc; q.y = v[i+1]*sc; q.z = v[i+2]*sc; q.w = v[i+3]*sc;
        cvt_store4(q, Ph + base + i, Pl + base + i);
    }
}

// ---------------- embedding + positional encoding -> fp32 + planes ----------------
__global__ void __launch_bounds__(256) embed_kernel(const int* __restrict__ src,
                                                    const float* __restrict__ emb,
                                                    float* __restrict__ X,
                                                    bf16* __restrict__ Xh,
                                                    bf16* __restrict__ Xl)
{
    int row = blockIdx.x;
    int s = row >> 1, b = row & 1;
    int tok = src[b*S_ + s];
    const float* e = emb + (size_t)tok*D_;
    size_t rb = (size_t)row*D_;
    const float c = -9.210340371976184f / (float)D_;
    #pragma unroll
    for (int i = 0; i < 4; i++) {
        int d = threadIdx.x + (i << 8);
        int ev = d & ~1;
        float div = expf((float)ev * c);
        float arg = (float)s * div;
        float pe = (d & 1) ? cosf(arg) : sinf(arg);
        float x = e[d]*32.0f + pe;
        X[rb + d] = x;
        cvt_store1(x, &Xh[rb + d], &Xl[rb + d]);
    }
}

// ---------------- distinct-source layer weights ----------------------------------
__global__ void dw_kernel(const float* __restrict__ lw, float* __restrict__ dw)
{
    int l = threadIdx.x;
    if (l >= L_) return;
    int n = l + 1;
    float w[17];
    float mx = -1e30f;
    for (int j = 0; j < n; j++) { w[j] = lw[l*(L_+1) + j]; mx = fmaxf(mx, w[j]); }
    float s = 0.f;
    for (int j = 0; j < n; j++) { w[j] = expf(w[j] - mx); s += w[j]; }
    for (int j = 0; j < n; j++) w[j] /= s;
    if (l == 0) dw[0] = w[0];
    else for (int j = 0; j < l; j++) dw[l*16 + j] = w[j+1] + ((j == l-1) ? w[0] : 0.f);
}

// ---------------- residual add (x + r0 + r1) + LayerNorm -> fp32 + planes ---------
__global__ void __launch_bounds__(256) addln3_kernel(const float* __restrict__ x,
                                                     const float* __restrict__ r0,
                                                     const float* __restrict__ r1,
                                                     const float* __restrict__ g,
                                                     const float* __restrict__ be,
                                                     float* __restrict__ outf,
                                                     bf16* __restrict__ outh,
                                                     bf16* __restrict__ outl)
{
    int row = blockIdx.x;
    const float* xr  = x  + (size_t)row*D_;
    const float* rr0 = r0 + (size_t)row*D_;
    const float* rr1 = r1 + (size_t)row*D_;
    int lane = threadIdx.x & 31, wid = threadIdx.x >> 5;
    float v[4];
    float s = 0.f, sq = 0.f;
    #pragma unroll
    for (int i = 0; i < 4; i++) {
        int d = threadIdx.x + (i << 8);
        float a = xr[d] + rr0[d] + rr1[d];
        v[i] = a; s += a; sq += a*a;
    }
    #pragma unroll
    for (int o = 16; o; o >>= 1) {
        s  += __shfl_xor_sync(0xffffffffu, s, o);
        sq += __shfl_xor_sync(0xffffffffu, sq, o);
    }
    __shared__ float shs[8], shq[8], mv[2];
    if (lane == 0) { shs[wid] = s; shq[wid] = sq; }
    __syncthreads();
    if (wid == 0) {
        float a = (lane < 8) ? shs[lane] : 0.f;
        float bsum = (lane < 8) ? shq[lane] : 0.f;
        #pragma unroll
        for (int o = 4; o; o >>= 1) {
            a += __shfl_xor_sync(0xffffffffu, a, o);
            bsum += __shfl_xor_sync(0xffffffffu, bsum, o);
        }
        if (lane == 0) {
            float mean = a * (1.f/ (float)D_);
            float var  = bsum * (1.f/ (float)D_) - mean*mean;
            mv[0] = mean; mv[1] = rsqrtf(var + 1e-5f);
        }
    }
    __syncthreads();
    float mean = mv[0], rstd = mv[1];
    size_t rb = (size_t)row*D_;
    #pragma unroll
    for (int i = 0; i < 4; i++) {
        int d = threadIdx.x + (i << 8);
        float o = (v[i] - mean)*rstd*g[d] + be[d];
        outf[rb + d] = o;
        cvt_store1(o, &outh[rb + d], &outl[rb + d]);
    }
}

// ---------------- SNN scan (block version, 2 partial inputs) -> bf16 spikes -------
__global__ void __launch_bounds__(256) snn_kernel(const float* __restrict__ cur0,
                                                  const float* __restrict__ cur1,
                                                  bf16* __restrict__ spikes)
{
    int b = blockIdx.x;
    int lane = threadIdx.x & 31, wid = threadIdx.x >> 5;
    float mem[4] = {0.f,0.f,0.f,0.f};
    float thr[4] = {1.f,1.f,1.f,1.f};
    __shared__ float sh[8];
    __shared__ float tot[2];
    for (int t = 0; t < S_; t++) {
        float p = mem[0]+mem[1]+mem[2]+mem[3];
        #pragma unroll
        for (int o = 16; o; o >>= 1) p += __shfl_xor_sync(0xffffffffu, p, o);
        if (lane == 0) sh[wid] = p;
        __syncthreads();
        if (wid == 0) {
            float v = (lane < 8) ? sh[lane] : 0.f;
            #pragma unroll
            for (int o = 4; o; o >>= 1) v += __shfl_xor_sync(0xffffffffu, v, o);
            if (lane == 0) tot[t & 1] = v;
        }
        __syncthreads();
        float M = tot[t & 1];
        const float* cr0 = cur0 + ((size_t)t*B_ + b)*D_;
        const float* cr1 = cur1 + ((size_t)t*B_ + b)*D_;
        bf16*        sr  = spikes + ((size_t)t*B_ + b)*D_;
        #pragma unroll
        for (int i = 0; i < 4; i++) {
            int d = threadIdx.x + (i << 8);
            float c  = cr0[d] + cr1[d] - 0.1f*M;
            float m2 = 0.9f*mem[i] + c;
            float sp = (m2 >= thr[i]) ? 1.f : 0.f;
            mem[i] = m2 - sp*thr[i];
            thr[i] = 0.9f*thr[i] + 0.1f*sp;
            sr[d] = __float2bfloat16(sp);
        }
    }
}

// ---------------- host orchestration ---------------------------------------------
extern "C" void kernel_launch(void* const* d_in, const int* in_sizes, int n_in,
                              void* d_out, int out_size)
{
    const int*   src  = (const int*)  d_in[0];
    const float* emb  = (const float*)d_in[1];
    const float* Wq   = (const float*)d_in[2];
    const float* bq   = (const float*)d_in[3];
    const float* Wk   = (const float*)d_in[4];
    const float* bk   = (const float*)d_in[5];
    const float* Wv   = (const float*)d_in[6];
    const float* bv   = (const float*)d_in[7];
    const float* Wo   = (const float*)d_in[8];
    const float* bo   = (const float*)d_in[9];
    const float* lw   = (const float*)d_in[10];
    const float* Wsnn = (const float*)d_in[11];
    const float* bsnn = (const float*)d_in[12];
    const float* W1   = (const float*)d_in[13];
    const float* b1   = (const float*)d_in[14];
    const float* W2   = (const float*)d_in[15];
    const float* b2   = (const float*)d_in[16];
    const float* g1   = (const float*)d_in[17];
    const float* be1  = (const float*)d_in[18];
    const float* g2   = (const float*)d_in[19];
    const float* be2  = (const float*)d_in[20];
    const float* Wout = (const float*)d_in[21];
    const float* bout = (const float*)d_in[22];
    float* out = (float*)d_out;

    float *x0,*lo,*sc,*xa,*t2,*cmbf,*dw;
    cudaGetSymbolAddress((void**)&x0, g_x0);
    cudaGetSymbolAddress((void**)&lo, g_lo);
    cudaGetSymbolAddress((void**)&sc, g_sc);
    cudaGetSymbolAddress((void**)&xa, g_xa);
    cudaGetSymbolAddress((void**)&t2, g_t2);
    cudaGetSymbolAddress((void**)&cmbf, g_cmbf);
    cudaGetSymbolAddress((void**)&dw, g_dw);
    float* t2b = t2 + SBD_;

    bf16 *x0h,*x0l,*loh,*lol,*qh,*ql,*kh,*kl,*vh,*vl,*sch,*scl,*combh,*combl,*xah,*xal,*sph,*tffh,*tffl;
    cudaGetSymbolAddress((void**)&x0h, g_x0h);   cudaGetSymbolAddress((void**)&x0l, g_x0l);
    cudaGetSymbolAddress((void**)&loh, g_loh);   cudaGetSymbolAddress((void**)&lol, g_lol);
    cudaGetSymbolAddress((void**)&qh,  g_qh);    cudaGetSymbolAddress((void**)&ql,  g_ql);
    cudaGetSymbolAddress((void**)&kh,  g_kh);    cudaGetSymbolAddress((void**)&kl,  g_kl);
    cudaGetSymbolAddress((void**)&vh,  g_vh);    cudaGetSymbolAddress((void**)&vl,  g_vl);
    cudaGetSymbolAddress((void**)&sch, g_sch);   cudaGetSymbolAddress((void**)&scl, g_scl);
    cudaGetSymbolAddress((void**)&combh, g_combh); cudaGetSymbolAddress((void**)&combl, g_combl);
    cudaGetSymbolAddress((void**)&xah, g_xah);   cudaGetSymbolAddress((void**)&xal, g_xal);
    cudaGetSymbolAddress((void**)&sph, g_sph);
    cudaGetSymbolAddress((void**)&tffh, g_tffh); cudaGetSymbolAddress((void**)&tffl, g_tffl);

    bf16 *wqh,*wql,*wkh,*wkl,*wvh,*wvl,*woh,*wol,*wsh,*wsl,*w1h,*w1l,*w2h,*w2l,*wouth,*woutl;
    cudaGetSymbolAddress((void**)&wqh, g_wqh);   cudaGetSymbolAddress((void**)&wql, g_wql);
    cudaGetSymbolAddress((void**)&wkh, g_wkh);   cudaGetSymbolAddress((void**)&wkl, g_wkl);
    cudaGetSymbolAddress((void**)&wvh, g_wvh);   cudaGetSymbolAddress((void**)&wvl, g_wvl);
    cudaGetSymbolAddress((void**)&woh, g_woh);   cudaGetSymbolAddress((void**)&wol, g_wol);
    cudaGetSymbolAddress((void**)&wsh, g_wsh);   cudaGetSymbolAddress((void**)&wsl, g_wsl);
    cudaGetSymbolAddress((void**)&w1h, g_w1h);   cudaGetSymbolAddress((void**)&w1l, g_w1l);
    cudaGetSymbolAddress((void**)&w2h, g_w2h);   cudaGetSymbolAddress((void**)&w2l, g_w2l);
    cudaGetSymbolAddress((void**)&wouth, g_wouth); cudaGetSymbolAddress((void**)&woutl, g_woutl);

    // ---- weight pre-split (memory-bound) ----
    const int NW = L_*D_*D_;
    const int NF = L_*D_*FF_;
    cvtw_kernel<<<NW/1024, 256>>>(Wq, wqh, wql, NW);
    cvtw_kernel<<<NW/1024, 256>>>(Wk, wkh, wkl, NW);
    cvtw_kernel<<<NW/1024, 256>>>(Wv, wvh, wvl, NW);
    cvtw_kernel<<<NW/1024, 256>>>(Wo, woh, wol, NW);
    cvtw_kernel<<<NW/1024, 256>>>(Wsnn, wsh, wsl, NW);
    cvtw_kernel<<<NF/1024, 256>>>(W1, w1h, w1l, NF);
    cvtw_kernel<<<NF/1024, 256>>>(W2, w2h, w2l, NF);
    cvtwout_kernel<<<dim3(NPV_/256, D_), 256>>>(Wout, wouth, woutl);

    embed_kernel<<<SB_, 256>>>(src, emb, x0, x0h, x0l);
    dw_kernel<<<1, 32>>>(lw, dw);

    for (int l = 0; l < L_; l++) {
        int nsrc = (l == 0) ? 1 : l;
        const bf16* sbh = (l == 0) ? x0h : loh;
        const bf16* sbl = (l == 0) ? x0l : lol;
        const bf16* xinh = (l == 0) ? x0h : (loh + (size_t)(l-1)*SBD_);
        const bf16* xinl = (l == 0) ? x0l : (lol + (size_t)(l-1)*SBD_);
        const float* xinf = (l == 0) ? x0 : (lo + (size_t)(l-1)*SBD_);

        // K, V (all distinct sources), Q projections -> planes  (R6 launch set)
        gemm_wmma<1,false,false,false><<<dim3(D_/128, nsrc*4), 256>>>(
            D_, D_, sbh, sbl, D_, wkh + (size_t)l*D_*D_, wkl + (size_t)l*D_*D_, D_,
            bk + l*D_, nullptr, kh, kl, D_);
        gemm_wmma<1,false,false,false><<<dim3(D_/128, nsrc*4), 256>>>(
            D_, D_, sbh, sbl, D_, wvh + (size_t)l*D_*D_, wvl + (size_t)l*D_*D_, D_,
            bv + l*D_, nullptr, vh, vl, D_);
        gemm_wmma<1,false,false,false><<<dim3(D_/128, SB_/128), 256>>>(
            D_, D_, xinh, xinl, D_, wqh + (size_t)l*D_*D_, wql + (size_t)l*D_*D_, D_,
            bq + l*D_, nullptr, qh, ql, D_);

        qk_wmma<<<dim3(2, 2, nsrc*16), 256>>>(qh, ql, kh, kl, sc);
        softmax_kernel<<<nsrc*512, 256>>>(sc, sch, scl, dw + l*16);

        // chunked comb: fp32 atomic accumulate, then convert to planes
        cudaMemsetAsync(cmbf, 0, SBD_*sizeof(float));
        int nchunk = (nsrc + 3) / 4;
        comb_wmma<<<dim3(1, 2, 16*nchunk), 256>>>(nsrc, sch, scl, vh, vl, cmbf);
        cvtw_kernel<<<SBD_/1024, 256>>>(cmbf, combh, combl, SBD_);

        // Wo projection split-K=2 -> partials; add+LN(3) -> xa fp32 + planes
        gemm_wmma_sk<<<dim3(D_/128, SB_/128, 2), 256>>>(
            D_, D_/2, combh, combl, D_, woh + (size_t)l*D_*D_, wol + (size_t)l*D_*D_, D_,
            bo + l*D_, t2, D_, SBD_);
        addln3_kernel<<<SB_, 256>>>(xinf, t2, t2b, g1 + l*D_, be1 + l*D_, xa, xah, xal);

        // SNN projection split-K=2 -> partials; scan sums them -> bf16 spikes
        gemm_wmma_sk<<<dim3(D_/128, SB_/128, 2), 256>>>(
            D_, D_/2, xah, xal, D_, wsh + (size_t)l*D_*D_, wsl + (size_t)l*D_*D_, D_,
            bsnn + l*D_, t2, D_, SBD_);
        snn_kernel<<<B_, 256>>>(t2, t2b, sph);

        // FFN: FF1 (A exact bf16, ReLU) -> planes; FF2 split-K=2; add+LN(3) -> lo[l]
        gemm_wmma<1,true,false,true><<<dim3(FF_/128, SB_/128), 256>>>(
            FF_, D_, sph, sph, D_, w1h + (size_t)l*D_*FF_, w1l + (size_t)l*D_*FF_, FF_,
            b1 + l*FF_, nullptr, tffh, tffl, FF_);
        gemm_wmma_sk<<<dim3(D_/128, SB_/128, 2), 256>>>(
            D_, FF_/2, tffh, tffl, FF_, w2h + (size_t)l*FF_*D_, w2l + (size_t)l*FF_*D_, D_,
            b2 + l*D_, t2, D_, SBD_);
        addln3_kernel<<<SB_, 256>>>(xa, t2, t2b, g2 + l*D_, be2 + l*D_,
                                    lo + (size_t)l*SBD_,
                                    loh + (size_t)l*SBD_, lol + (size_t)l*SBD_);
    }

    // final vocab projection (fp32 out, fused [S,B]->[B,S] transpose)
    gemm_wmma<0,false,true,false><<<dim3((V_+127)/128, SB_/128), 256>>>(
        V_, D_, loh + (size_t)15*SBD_, lol + (size_t)15*SBD_, D_,
        wouth, woutl, NPV_, bout, out, nullptr, nullptr, V_);
}

// round 16
// speedup vs baseline: 1.8095x; 1.0873x over previous
#include <cuda_runtime.h>
#include <cuda_bf16.h>
#include <mma.h>
#include <math.h>

using namespace nvcuda;

#define B_   2
#define S_   256
#define D_   1024
#define H_   8
#define L_   16
#define FF_  2048
#define V_   50257
#define NPV_ 50432
#define HD_  128
#define SB_  (S_*B_)          // 512
#define SBD_ (SB_*D_)         // 524288

typedef __nv_bfloat16 bf16;

// ---------------- fp32 masters ----------------------------------------------------
static __device__ float g_x0[SBD_];
static __device__ float g_lo[L_*SBD_];
static __device__ float g_sc[15*16*S_*S_];
static __device__ float g_xa[SBD_];
static __device__ float g_t2[4*SBD_];       // split-K partials (up to 4)
static __device__ float g_cmbf[SBD_];       // comb fp32 accumulator
static __device__ float g_dw[L_*16];
static __device__ float g_zero[2048];       // zero bias for split-K halves >0

// ---------------- bf16 hi/lo activation planes ------------------------------------
static __device__ __align__(16) bf16 g_x0h[SBD_],  g_x0l[SBD_];
static __device__ __align__(16) bf16 g_loh[L_*SBD_], g_lol[L_*SBD_];
static __device__ __align__(16) bf16 g_qh[SBD_],   g_ql[SBD_];
static __device__ __align__(16) bf16 g_kh[15*SBD_], g_kl[15*SBD_];
static __device__ __align__(16) bf16 g_vh[15*SBD_], g_vl[15*SBD_];
static __device__ __align__(16) bf16 g_sch[15*16*S_*S_], g_scl[15*16*S_*S_];
static __device__ __align__(16) bf16 g_combh[SBD_], g_combl[SBD_];
static __device__ __align__(16) bf16 g_xah[SBD_],  g_xal[SBD_];
static __device__ __align__(16) bf16 g_sph[SBD_];
static __device__ __align__(16) bf16 g_tffh[SB_*FF_], g_tffl[SB_*FF_];

// ---------------- bf16 hi/lo weight planes ----------------------------------------
static __device__ __align__(16) bf16 g_wqh[L_*D_*D_],  g_wql[L_*D_*D_];
static __device__ __align__(16) bf16 g_wkh[L_*D_*D_],  g_wkl[L_*D_*D_];
static __device__ __align__(16) bf16 g_wvh[L_*D_*D_],  g_wvl[L_*D_*D_];
static __device__ __align__(16) bf16 g_woh[L_*D_*D_],  g_wol[L_*D_*D_];
static __device__ __align__(16) bf16 g_wsh[L_*D_*D_],  g_wsl[L_*D_*D_];
static __device__ __align__(16) bf16 g_w1h[L_*D_*FF_], g_w1l[L_*D_*FF_];
static __device__ __align__(16) bf16 g_w2h[L_*FF_*D_], g_w2l[L_*FF_*D_];
static __device__ __align__(16) bf16 g_wouth[D_*NPV_], g_woutl[D_*NPV_];

// ================== split helpers =================================================
__device__ __forceinline__ void cvt_store4(float4 v, bf16* hp, bf16* lp)
{
    bf16 h0 = __float2bfloat16(v.x), h1 = __float2bfloat16(v.y);
    bf16 h2 = __float2bfloat16(v.z), h3 = __float2bfloat16(v.w);
    bf16 l0 = __float2bfloat16(v.x - __bfloat162float(h0));
    bf16 l1 = __float2bfloat16(v.y - __bfloat162float(h1));
    bf16 l2 = __float2bfloat16(v.z - __bfloat162float(h2));
    bf16 l3 = __float2bfloat16(v.w - __bfloat162float(h3));
    __nv_bfloat162 a; a.x = h0; a.y = h1;
    __nv_bfloat162 b; b.x = h2; b.y = h3;
    __nv_bfloat162 c; c.x = l0; c.y = l1;
    __nv_bfloat162 d; d.x = l2; d.y = l3;
    *(__nv_bfloat162*)(hp)   = a;  *(__nv_bfloat162*)(hp+2) = b;
    *(__nv_bfloat162*)(lp)   = c;  *(__nv_bfloat162*)(lp+2) = d;
}
__device__ __forceinline__ void cvt_store1(float x, bf16* hp, bf16* lp)
{
    bf16 h = __float2bfloat16(x);
    *hp = h;
    *lp = __float2bfloat16(x - __bfloat162float(h));
}

// ================== conversion kernels ============================================
__global__ void __launch_bounds__(256) cvtw_kernel(const float* __restrict__ src,
                                                   bf16* __restrict__ h,
                                                   bf16* __restrict__ l, int n)
{
    int i = (blockIdx.x*256 + threadIdx.x)*4;
    if (i >= n) return;
    float4 v = *(const float4*)(src + i);
    cvt_store4(v, h + i, l + i);
}
// sum of two fp32 partials -> bf16 planes (for split-K Q projection)
__global__ void __launch_bounds__(256) cvt2_kernel(const float* __restrict__ a,
                                                   const float* __restrict__ b,
                                                   bf16* __restrict__ h,
                                                   bf16* __restrict__ l)
{
    int i = (blockIdx.x*256 + threadIdx.x)*4;
    float4 va = *(const float4*)(a + i);
    float4 vb = *(const float4*)(b + i);
    va.x += vb.x; va.y += vb.y; va.z += vb.z; va.w += vb.w;
    cvt_store4(va, h + i, l + i);
}
__global__ void __launch_bounds__(256) cvtwout_kernel(const float* __restrict__ src,
                                                      bf16* __restrict__ h,
                                                      bf16* __restrict__ l)
{
    int n = blockIdx.x*256 + threadIdx.x;
    int row = blockIdx.y;
    float x = (n < V_) ? src[(size_t)row*V_ + n] : 0.f;
    cvt_store1(x, &h[(size_t)row*NPV_ + n], &l[(size_t)row*NPV_ + n]);
}

// ================== GEMM core (R6 body, static smem) ==============================
template<int OM, bool RELU, bool OUTBS, bool AEX>
__device__ __forceinline__ void gemm_core(
    int N, int K,
    const bf16* __restrict__ Ahg, const bf16* __restrict__ Alg, int lda,
    const bf16* __restrict__ Bhg, const bf16* __restrict__ Blg, int ldb,
    const float* __restrict__ bias,
    float* __restrict__ Cf, bf16* __restrict__ Ch, bf16* __restrict__ Cl, int ldc,
    int m0, int n0, char* smraw)
{
    bf16* sAh = (bf16*)(smraw);
    bf16* sAl = (bf16*)(smraw + 10240);
    bf16* sBh = (bf16*)(smraw + 20480);
    bf16* sBl = (bf16*)(smraw + 29184);
    float* stage = (float*)smraw;

    int tid = threadIdx.x;
    int warp = tid >> 5;
    int wm = warp >> 2, wn = warp & 3;

    wmma::fragment<wmma::accumulator, 16, 16, 16, float> acc[4][2];
    #pragma unroll
    for (int i = 0; i < 4; i++)
        #pragma unroll
        for (int j = 0; j < 2; j++)
            wmma::fill_fragment(acc[i][j], 0.0f);

    int arow = tid >> 1, akq = (tid & 1) << 4;
    int bkr = tid >> 3, bnq = (tid & 7) << 4;

    const bf16* Ah0 = Ahg + (size_t)(m0 + arow)*lda + akq;
    const bf16* Al0 = AEX ? Ah0 : (Alg + (size_t)(m0 + arow)*lda + akq);

    for (int k0 = 0; k0 < K; k0 += 32) {
        {
            const uint4* ph = (const uint4*)(Ah0 + k0);
            uint4 h0 = ph[0], h1 = ph[1];
            ((uint4*)(sAh + arow*40 + akq))[0] = h0;
            ((uint4*)(sAh + arow*40 + akq))[1] = h1;
            if (!AEX) {
                const uint4* pl = (const uint4*)(Al0 + k0);
                uint4 l0 = pl[0], l1 = pl[1];
                ((uint4*)(sAl + arow*40 + akq))[0] = l0;
                ((uint4*)(sAl + arow*40 + akq))[1] = l1;
            }
        }
        {
            const uint4* ph = (const uint4*)(Bhg + (size_t)(k0 + bkr)*ldb + n0 + bnq);
            const uint4* pl = (const uint4*)(Blg + (size_t)(k0 + bkr)*ldb + n0 + bnq);
            uint4 h0 = ph[0], h1 = ph[1];
            uint4 l0 = pl[0], l1 = pl[1];
            ((uint4*)(sBh + bkr*136 + bnq))[0] = h0;
            ((uint4*)(sBh + bkr*136 + bnq))[1] = h1;
            ((uint4*)(sBl + bkr*136 + bnq))[0] = l0;
            ((uint4*)(sBl + bkr*136 + bnq))[1] = l1;
        }
        __syncthreads();
        #pragma unroll
        for (int kk = 0; kk < 32; kk += 16) {
            wmma::fragment<wmma::matrix_b, 16, 16, 16, bf16, wmma::row_major> fbh[2], fbl[2];
            #pragma unroll
            for (int j = 0; j < 2; j++) {
                wmma::load_matrix_sync(fbh[j], &sBh[kk*136 + wn*32 + j*16], 136);
                wmma::load_matrix_sync(fbl[j], &sBl[kk*136 + wn*32 + j*16], 136);
            }
            #pragma unroll
            for (int i = 0; i < 4; i++) {
                wmma::fragment<wmma::matrix_a, 16, 16, 16, bf16, wmma::row_major> fah, fal;
                wmma::load_matrix_sync(fah, &sAh[(wm*64 + i*16)*40 + kk], 40);
                if (!AEX) wmma::load_matrix_sync(fal, &sAl[(wm*64 + i*16)*40 + kk], 40);
                #pragma unroll
                for (int j = 0; j < 2; j++) {
                    wmma::mma_sync(acc[i][j], fah, fbh[j], acc[i][j]);
                    wmma::mma_sync(acc[i][j], fah, fbl[j], acc[i][j]);
                    if (!AEX) wmma::mma_sync(acc[i][j], fal, fbh[j], acc[i][j]);
                }
            }
        }
        __syncthreads();
    }

    const bool valigned = ((ldc & 3) == 0);
    #pragma unroll
    for (int ph = 0; ph < 2; ph++) {
        if (wm == ph) {
            #pragma unroll
            for (int i = 0; i < 4; i++)
                #pragma unroll
                for (int j = 0; j < 2; j++)
                    wmma::store_matrix_sync(&stage[(i*16)*132 + wn*32 + j*16],
                                            acc[i][j], 132, wmma::mem_row_major);
        }
        __syncthreads();
        int r = tid >> 2;
        int c0 = (tid & 3) << 5;
        int m = m0 + ph*64 + r;
        int orow = OUTBS ? ((m & 1)*S_ + (m >> 1)) : m;
        const float* srow = stage + r*132 + c0;
        int nb = n0 + c0;
        if (OM == 1) {
            bf16* hrow = Ch + (size_t)orow*ldc;
            bf16* lrow = Cl + (size_t)orow*ldc;
            #pragma unroll
            for (int g = 0; g < 8; g++) {
                float4 v = *(const float4*)(srow + g*4);
                float4 bb = *(const float4*)(bias + nb + g*4);
                v.x += bb.x; v.y += bb.y; v.z += bb.z; v.w += bb.w;
                if (RELU) {
                    v.x = fmaxf(v.x, 0.f); v.y = fmaxf(v.y, 0.f);
                    v.z = fmaxf(v.z, 0.f); v.w = fmaxf(v.w, 0.f);
                }
                cvt_store4(v, hrow + nb + g*4, lrow + nb + g*4);
            }
        } else {
            float* crow = Cf + (size_t)orow*ldc;
            if (valigned && nb + 32 <= N) {
                #pragma unroll
                for (int g = 0; g < 8; g++) {
                    float4 v = *(const float4*)(srow + g*4);
                    float4 bb = *(const float4*)(bias + nb + g*4);
                    v.x += bb.x; v.y += bb.y; v.z += bb.z; v.w += bb.w;
                    if (RELU) {
                        v.x = fmaxf(v.x, 0.f); v.y = fmaxf(v.y, 0.f);
                        v.z = fmaxf(v.z, 0.f); v.w = fmaxf(v.w, 0.f);
                    }
                    *(float4*)(crow + nb + g*4) = v;
                }
            } else {
                for (int g = 0; g < 32; g++) {
                    int n = nb + g;
                    if (n < N) {
                        float v = srow[g] + bias[n];
                        if (RELU) v = fmaxf(v, 0.f);
                        crow[n] = v;
                    }
                }
            }
        }
        __syncthreads();
    }
}

template<int OM, bool RELU, bool OUTBS, bool AEX>
__global__ void __launch_bounds__(256) gemm_wmma(
    int N, int K,
    const bf16* __restrict__ Ahg, const bf16* __restrict__ Alg, int lda,
    const bf16* __restrict__ Bhg, const bf16* __restrict__ Blg, int ldb,
    const float* __restrict__ bias,
    float* __restrict__ Cf, bf16* __restrict__ Ch, bf16* __restrict__ Cl, int ldc)
{
    __shared__ __align__(16) char smraw[37888];
    gemm_core<OM, RELU, OUTBS, AEX>(N, K, Ahg, Alg, lda, Bhg, Blg, ldb, bias,
                                    Cf, Ch, Cl, ldc,
                                    blockIdx.y << 7, blockIdx.x << 7, smraw);
}

// split-K GEMM (any split count via gridDim.z): partial z -> Cf + z*pstride.
__global__ void __launch_bounds__(256) gemm_wmma_sk(
    int N, int Kpart,
    const bf16* __restrict__ Ahg, const bf16* __restrict__ Alg, int lda,
    const bf16* __restrict__ Bhg, const bf16* __restrict__ Blg, int ldb,
    const float* __restrict__ bias,
    float* __restrict__ Cf, int ldc, int pstride)
{
    __shared__ __align__(16) char smraw[37888];
    int z = blockIdx.z;
    gemm_core<0, false, false, false>(N, Kpart,
        Ahg + z*Kpart, Alg + z*Kpart, lda,
        Bhg + (size_t)z*Kpart*ldb, Blg + (size_t)z*Kpart*ldb, ldb,
        z ? g_zero : bias,
        Cf + (size_t)z*pstride, nullptr, nullptr, ldc,
        blockIdx.y << 7, blockIdx.x << 7, smraw);
}

// ================== QK scores (NT, R6 body) =======================================
__global__ void __launch_bounds__(256) qk_wmma(
    const bf16* __restrict__ Qh, const bf16* __restrict__ Ql,
    const bf16* __restrict__ Kh, const bf16* __restrict__ Kl,
    float* __restrict__ P)
{
    __shared__ __align__(16) char smraw[40960];
    bf16* sAh = (bf16*)(smraw);
    bf16* sAl = (bf16*)(smraw + 10240);
    bf16* sBh = (bf16*)(smraw + 20480);
    bf16* sBl = (bf16*)(smraw + 30720);

    int z = blockIdx.z;
    int src = z >> 4, bh = z & 15;
    const bf16* Aqh = Qh + bh*HD_;
    const bf16* Aql = Ql + bh*HD_;
    const bf16* Bkh = Kh + (size_t)src*SBD_ + bh*HD_;
    const bf16* Bkl = Kl + (size_t)src*SBD_ + bh*HD_;
    float* Cp = P + (size_t)z*S_*S_;

    int tid = threadIdx.x;
    int warp = tid >> 5;
    int wm = warp >> 2, wn = warp & 3;
    int m0 = blockIdx.y << 7, n0 = blockIdx.x << 7;

    wmma::fragment<wmma::accumulator, 16, 16, 16, float> acc[4][2];
    #pragma unroll
    for (int i = 0; i < 4; i++)
        #pragma unroll
        for (int j = 0; j < 2; j++)
            wmma::fill_fragment(acc[i][j], 0.0f);

    int arow = tid >> 1, akq = (tid & 1) << 4;

    for (int k0 = 0; k0 < HD_; k0 += 32) {
        size_t aoff = (size_t)(m0 + arow)*(B_*D_) + k0 + akq;
        size_t boff = (size_t)(n0 + arow)*(B_*D_) + k0 + akq;
        uint4 ah0 = ((const uint4*)(Aqh + aoff))[0], ah1 = ((const uint4*)(Aqh + aoff))[1];
        uint4 al0 = ((const uint4*)(Aql + aoff))[0], al1 = ((const uint4*)(Aql + aoff))[1];
        uint4 bh0 = ((const uint4*)(Bkh + boff))[0], bh1 = ((const uint4*)(Bkh + boff))[1];
        uint4 bl0 = ((const uint4*)(Bkl + boff))[0], bl1 = ((const uint4*)(Bkl + boff))[1];
        ((uint4*)(sAh + arow*40 + akq))[0] = ah0; ((uint4*)(sAh + arow*40 + akq))[1] = ah1;
        ((uint4*)(sAl + arow*40 + akq))[0] = al0; ((uint4*)(sAl + arow*40 + akq))[1] = al1;
        ((uint4*)(sBh + arow*40 + akq))[0] = bh0; ((uint4*)(sBh + arow*40 + akq))[1] = bh1;
        ((uint4*)(sBl + arow*40 + akq))[0] = bl0; ((uint4*)(sBl + arow*40 + akq))[1] = bl1;
        __syncthreads();
        #pragma unroll
        for (int kk = 0; kk < 32; kk += 16) {
            wmma::fragment<wmma::matrix_b, 16, 16, 16, bf16, wmma::col_major> fbh[2], fbl[2];
            #pragma unroll
            for (int j = 0; j < 2; j++) {
                wmma::load_matrix_sync(fbh[j], &sBh[(wn*32 + j*16)*40 + kk], 40);
                wmma::load_matrix_sync(fbl[j], &sBl[(wn*32 + j*16)*40 + kk], 40);
            }
            #pragma unroll
            for (int i = 0; i < 4; i++) {
                wmma::fragment<wmma::matrix_a, 16, 16, 16, bf16, wmma::row_major> fah, fal;
                wmma::load_matrix_sync(fah, &sAh[(wm*64 + i*16)*40 + kk], 40);
                wmma::load_matrix_sync(fal, &sAl[(wm*64 + i*16)*40 + kk], 40);
                #pragma unroll
                for (int j = 0; j < 2; j++) {
                    wmma::mma_sync(acc[i][j], fah, fbh[j], acc[i][j]);
                    wmma::mma_sync(acc[i][j], fah, fbl[j], acc[i][j]);
                    wmma::mma_sync(acc[i][j], fal, fbh[j], acc[i][j]);
                }
            }
        }
        __syncthreads();
    }
    const float scale = 0.0883883476483184f;
    #pragma unroll
    for (int i = 0; i < 4; i++)
        #pragma unroll
        for (int j = 0; j < 2; j++) {
            #pragma unroll
            for (int e = 0; e < acc[i][j].num_elements; e++) acc[i][j].x[e] *= scale;
            wmma::store_matrix_sync(&Cp[(size_t)(m0 + wm*64 + i*16)*S_ + n0 + wn*32 + j*16],
                                    acc[i][j], S_, wmma::mem_row_major);
        }
}

// ================== comb: chunked sources (2 per chunk), fp32 atomic ==============
__global__ void __launch_bounds__(256) comb_wmma(
    int nsrc,
    const bf16* __restrict__ Ph, const bf16* __restrict__ Pl,
    const bf16* __restrict__ Vh, const bf16* __restrict__ Vl,
    float* __restrict__ Cc)
{
    __shared__ __align__(16) char smraw[37888];
    bf16* sAh = (bf16*)(smraw);
    bf16* sAl = (bf16*)(smraw + 10240);
    bf16* sBh = (bf16*)(smraw + 20480);
    bf16* sBl = (bf16*)(smraw + 29184);
    float* stage = (float*)smraw;

    int bh = blockIdx.z & 15, chunk = blockIdx.z >> 4;
    int b = bh >> 3, h = bh & 7;
    int s0 = chunk*2;
    int send = s0 + 2; if (send > nsrc) send = nsrc;
    int tid = threadIdx.x;
    int warp = tid >> 5;
    int wm = warp >> 2, wn = warp & 3;
    int m0 = blockIdx.y << 7;

    wmma::fragment<wmma::accumulator, 16, 16, 16, float> acc[4][2];
    #pragma unroll
    for (int i = 0; i < 4; i++)
        #pragma unroll
        for (int j = 0; j < 2; j++)
            wmma::fill_fragment(acc[i][j], 0.0f);

    int arow = tid >> 1, akq = (tid & 1) << 4;
    int bkr = tid >> 3, bnq = (tid & 7) << 4;

    for (int src = s0; src < send; src++) {
        const bf16* Ah0 = Ph + ((size_t)src*16 + bh)*S_*S_;
        const bf16* Al0 = Pl + ((size_t)src*16 + bh)*S_*S_;
        const bf16* Bh0 = Vh + (size_t)src*SBD_ + bh*HD_;
        const bf16* Bl0 = Vl + (size_t)src*SBD_ + bh*HD_;
        for (int k0 = 0; k0 < S_; k0 += 32) {
            size_t aoff = (size_t)(m0 + arow)*S_ + k0 + akq;
            size_t boff = (size_t)(k0 + bkr)*(B_*D_) + bnq;
            uint4 ah0 = ((const uint4*)(Ah0 + aoff))[0], ah1 = ((const uint4*)(Ah0 + aoff))[1];
            uint4 al0 = ((const uint4*)(Al0 + aoff))[0], al1 = ((const uint4*)(Al0 + aoff))[1];
            uint4 bh0 = ((const uint4*)(Bh0 + boff))[0], bh1 = ((const uint4*)(Bh0 + boff))[1];
            uint4 bl0 = ((const uint4*)(Bl0 + boff))[0], bl1 = ((const uint4*)(Bl0 + boff))[1];
            ((uint4*)(sAh + arow*40 + akq))[0] = ah0; ((uint4*)(sAh + arow*40 + akq))[1] = ah1;
            ((uint4*)(sAl + arow*40 + akq))[0] = al0; ((uint4*)(sAl + arow*40 + akq))[1] = al1;
            ((uint4*)(sBh + bkr*136 + bnq))[0] = bh0; ((uint4*)(sBh + bkr*136 + bnq))[1] = bh1;
            ((uint4*)(sBl + bkr*136 + bnq))[0] = bl0; ((uint4*)(sBl + bkr*136 + bnq))[1] = bl1;
            __syncthreads();
            #pragma unroll
            for (int kk = 0; kk < 32; kk += 16) {
                wmma::fragment<wmma::matrix_b, 16, 16, 16, bf16, wmma::row_major> fbh[2], fbl[2];
                #pragma unroll
                for (int j = 0; j < 2; j++) {
                    wmma::load_matrix_sync(fbh[j], &sBh[kk*136 + wn*32 + j*16], 136);
                    wmma::load_matrix_sync(fbl[j], &sBl[kk*136 + wn*32 + j*16], 136);
                }
                #pragma unroll
                for (int i = 0; i < 4; i++) {
                    wmma::fragment<wmma::matrix_a, 16, 16, 16, bf16, wmma::row_major> fah, fal;
                    wmma::load_matrix_sync(fah, &sAh[(wm*64 + i*16)*40 + kk], 40);
                    wmma::load_matrix_sync(fal, &sAl[(wm*64 + i*16)*40 + kk], 40);
                    #pragma unroll
                    for (int j = 0; j < 2; j++) {
                        wmma::mma_sync(acc[i][j], fah, fbh[j], acc[i][j]);
                        wmma::mma_sync(acc[i][j], fah, fbl[j], acc[i][j]);
                        wmma::mma_sync(acc[i][j], fal, fbh[j], acc[i][j]);
                    }
                }
            }
            __syncthreads();
        }
    }

    #pragma unroll
    for (int ph = 0; ph < 2; ph++) {
        if (wm == ph) {
            #pragma unroll
            for (int i = 0; i < 4; i++)
                #pragma unroll
                for (int j = 0; j < 2; j++)
                    wmma::store_matrix_sync(&stage[(i*16)*132 + wn*32 + j*16],
                                            acc[i][j], 132, wmma::mem_row_major);
        }
        __syncthreads();
        int r = tid >> 2;
        int c0 = (tid & 3) << 5;
        int qrow = m0 + ph*64 + r;
        float* crow = Cc + ((size_t)qrow*B_ + b)*D_ + h*HD_;
        const float* srow = stage + r*132 + c0;
        #pragma unroll
        for (int g = 0; g < 32; g++)
            atomicAdd(&crow[c0 + g], srow[g]);
        __syncthreads();
    }
}

// ---------------- softmax over keys + layer weight -> bf16 planes -----------------
__global__ void __launch_bounds__(256) softmax_kernel(const float* __restrict__ P,
                                                      bf16* __restrict__ Ph,
                                                      bf16* __restrict__ Pl,
                                                      const float* __restrict__ dwl)
{
    int r = blockIdx.x*8 + (threadIdx.x >> 5);
    int lane = threadIdx.x & 31;
    const float* row = P + (size_t)r*256;
    float w = dwl[r >> 12];
    float v[8];
    #pragma unroll
    for (int i = 0; i < 8; i++) v[i] = row[lane*8 + i];
    float mx = v[0];
    #pragma unroll
    for (int i = 1; i < 8; i++) mx = fmaxf(mx, v[i]);
    #pragma unroll
    for (int o = 16; o; o >>= 1) mx = fmaxf(mx, __shfl_xor_sync(0xffffffffu, mx, o));
    float s = 0.f;
    #pragma unroll
    for (int i = 0; i < 8; i++) { v[i] = expf(v[i] - mx); s += v[i]; }
    #pragma unroll
    for (int o = 16; o; o >>= 1) s += __shfl_xor_sync(0xffffffffu, s, o);
    float sc = w / s;
    size_t base = (size_t)r*256 + lane*8;
    #pragma unroll
    for (int i = 0; i < 8; i += 4) {
        float4 q;
        q.x = v[i]*sc; q.y = v[i+1]*sc; q.z = v[i+2]*sc; q.w = v[i+3]*sc;
        cvt_store4(q, Ph + base + i, Pl + base + i);
    }
}

// ---------------- embedding + positional encoding -> fp32 + planes ----------------
__global__ void __launch_bounds__(256) embed_kernel(const int* __restrict__ src,
                                                    const float* __restrict__ emb,
                                                    float* __restrict__ X,
                                                    bf16* __restrict__ Xh,
                                                    bf16* __restrict__ Xl)
{
    int row = blockIdx.x;
    int s = row >> 1, b = row & 1;
    int tok = src[b*S_ + s];
    const float* e = emb + (size_t)tok*D_;
    size_t rb = (size_t)row*D_;
    const float c = -9.210340371976184f / (float)D_;
    #pragma unroll
    for (int i = 0; i < 4; i++) {
        int d = threadIdx.x + (i << 8);
        int ev = d & ~1;
        float div = expf((float)ev * c);
        float arg = (float)s * div;
        float pe = (d & 1) ? cosf(arg) : sinf(arg);
        float x = e[d]*32.0f + pe;
        X[rb + d] = x;
        cvt_store1(x, &Xh[rb + d], &Xl[rb + d]);
    }
}

// ---------------- distinct-source layer weights ----------------------------------
__global__ void dw_kernel(const float* __restrict__ lw, float* __restrict__ dw)
{
    int l = threadIdx.x;
    if (l >= L_) return;
    int n = l + 1;
    float w[17];
    float mx = -1e30f;
    for (int j = 0; j < n; j++) { w[j] = lw[l*(L_+1) + j]; mx = fmaxf(mx, w[j]); }
    float s = 0.f;
    for (int j = 0; j < n; j++) { w[j] = expf(w[j] - mx); s += w[j]; }
    for (int j = 0; j < n; j++) w[j] /= s;
    if (l == 0) dw[0] = w[0];
    else for (int j = 0; j < l; j++) dw[l*16 + j] = w[j+1] + ((j == l-1) ? w[0] : 0.f);
}

// ---------------- residual add (x + N partials) + LayerNorm -----------------------
template<int NP>
__global__ void __launch_bounds__(256) addln_kernel(const float* __restrict__ x,
                                                    const float* __restrict__ r0,
                                                    int pstride,
                                                    const float* __restrict__ g,
                                                    const float* __restrict__ be,
                                                    float* __restrict__ outf,
                                                    bf16* __restrict__ outh,
                                                    bf16* __restrict__ outl)
{
    int row = blockIdx.x;
    const float* xr = x + (size_t)row*D_;
    int lane = threadIdx.x & 31, wid = threadIdx.x >> 5;
    float v[4];
    float s = 0.f, sq = 0.f;
    #pragma unroll
    for (int i = 0; i < 4; i++) {
        int d = threadIdx.x + (i << 8);
        float a = xr[d];
        #pragma unroll
        for (int p = 0; p < NP; p++)
            a += r0[(size_t)p*pstride + (size_t)row*D_ + d];
        v[i] = a; s += a; sq += a*a;
    }
    #pragma unroll
    for (int o = 16; o; o >>= 1) {
        s  += __shfl_xor_sync(0xffffffffu, s, o);
        sq += __shfl_xor_sync(0xffffffffu, sq, o);
    }
    __shared__ float shs[8], shq[8], mv[2];
    if (lane == 0) { shs[wid] = s; shq[wid] = sq; }
    __syncthreads();
    if (wid == 0) {
        float a = (lane < 8) ? shs[lane] : 0.f;
        float bsum = (lane < 8) ? shq[lane] : 0.f;
        #pragma unroll
        for (int o = 4; o; o >>= 1) {
            a += __shfl_xor_sync(0xffffffffu, a, o);
            bsum += __shfl_xor_sync(0xffffffffu, bsum, o);
        }
        if (lane == 0) {
            float mean = a * (1.f/ (float)D_);
            float var  = bsum * (1.f/ (float)D_) - mean*mean;
            mv[0] = mean; mv[1] = rsqrtf(var + 1e-5f);
        }
    }
    __syncthreads();
    float mean = mv[0], rstd = mv[1];
    size_t rb = (size_t)row*D_;
    #pragma unroll
    for (int i = 0; i < 4; i++) {
        int d = threadIdx.x + (i << 8);
        float o = (v[i] - mean)*rstd*g[d] + be[d];
        outf[rb + d] = o;
        cvt_store1(o, &outh[rb + d], &outl[rb + d]);
    }
}

// ---------------- SNN scan (block version, 2 partial inputs) -> bf16 spikes -------
__global__ void __launch_bounds__(256) snn_kernel(const float* __restrict__ cur0,
                                                  const float* __restrict__ cur1,
                                                  bf16* __restrict__ spikes)
{
    int b = blockIdx.x;
    int lane = threadIdx.x & 31, wid = threadIdx.x >> 5;
    float mem[4] = {0.f,0.f,0.f,0.f};
    float thr[4] = {1.f,1.f,1.f,1.f};
    __shared__ float sh[8];
    __shared__ float tot[2];
    for (int t = 0; t < S_; t++) {
        float p = mem[0]+mem[1]+mem[2]+mem[3];
        #pragma unroll
        for (int o = 16; o; o >>= 1) p += __shfl_xor_sync(0xffffffffu, p, o);
        if (lane == 0) sh[wid] = p;
        __syncthreads();
        if (wid == 0) {
            float v = (lane < 8) ? sh[lane] : 0.f;
            #pragma unroll
            for (int o = 4; o; o >>= 1) v += __shfl_xor_sync(0xffffffffu, v, o);
            if (lane == 0) tot[t & 1] = v;
        }
        __syncthreads();
        float M = tot[t & 1];
        const float* cr0 = cur0 + ((size_t)t*B_ + b)*D_;
        const float* cr1 = cur1 + ((size_t)t*B_ + b)*D_;
        bf16*        sr  = spikes + ((size_t)t*B_ + b)*D_;
        #pragma unroll
        for (int i = 0; i < 4; i++) {
            int d = threadIdx.x + (i << 8);
            float c  = cr0[d] + cr1[d] - 0.1f*M;
            float m2 = 0.9f*mem[i] + c;
            float sp = (m2 >= thr[i]) ? 1.f : 0.f;
            mem[i] = m2 - sp*thr[i];
            thr[i] = 0.9f*thr[i] + 0.1f*sp;
            sr[d] = __float2bfloat16(sp);
        }
    }
}

// ---------------- host orchestration ---------------------------------------------
extern "C" void kernel_launch(void* const* d_in, const int* in_sizes, int n_in,
                              void* d_out, int out_size)
{
    const int*   src  = (const int*)  d_in[0];
    const float* emb  = (const float*)d_in[1];
    const float* Wq   = (const float*)d_in[2];
    const float* bq   = (const float*)d_in[3];
    const float* Wk   = (const float*)d_in[4];
    const float* bk   = (const float*)d_in[5];
    const float* Wv   = (const float*)d_in[6];
    const float* bv   = (const float*)d_in[7];
    const float* Wo   = (const float*)d_in[8];
    const float* bo   = (const float*)d_in[9];
    const float* lw   = (const float*)d_in[10];
    const float* Wsnn = (const float*)d_in[11];
    const float* bsnn = (const float*)d_in[12];
    const float* W1   = (const float*)d_in[13];
    const float* b1   = (const float*)d_in[14];
    const float* W2   = (const float*)d_in[15];
    const float* b2   = (const float*)d_in[16];
    const float* g1   = (const float*)d_in[17];
    const float* be1  = (const float*)d_in[18];
    const float* g2   = (const float*)d_in[19];
    const float* be2  = (const float*)d_in[20];
    const float* Wout = (const float*)d_in[21];
    const float* bout = (const float*)d_in[22];
    float* out = (float*)d_out;

    float *x0,*lo,*sc,*xa,*t2,*cmbf,*dw;
    cudaGetSymbolAddress((void**)&x0, g_x0);
    cudaGetSymbolAddress((void**)&lo, g_lo);
    cudaGetSymbolAddress((void**)&sc, g_sc);
    cudaGetSymbolAddress((void**)&xa, g_xa);
    cudaGetSymbolAddress((void**)&t2, g_t2);
    cudaGetSymbolAddress((void**)&cmbf, g_cmbf);
    cudaGetSymbolAddress((void**)&dw, g_dw);
    float* t2b = t2 + SBD_;

    bf16 *x0h,*x0l,*loh,*lol,*qh,*ql,*kh,*kl,*vh,*vl,*sch,*scl,*combh,*combl,*xah,*xal,*sph,*tffh,*tffl;
    cudaGetSymbolAddress((void**)&x0h, g_x0h);   cudaGetSymbolAddress((void**)&x0l, g_x0l);
    cudaGetSymbolAddress((void**)&loh, g_loh);   cudaGetSymbolAddress((void**)&lol, g_lol);
    cudaGetSymbolAddress((void**)&qh,  g_qh);    cudaGetSymbolAddress((void**)&ql,  g_ql);
    cudaGetSymbolAddress((void**)&kh,  g_kh);    cudaGetSymbolAddress((void**)&kl,  g_kl);
    cudaGetSymbolAddress((void**)&vh,  g_vh);    cudaGetSymbolAddress((void**)&vl,  g_vl);
    cudaGetSymbolAddress((void**)&sch, g_sch);   cudaGetSymbolAddress((void**)&scl, g_scl);
    cudaGetSymbolAddress((void**)&combh, g_combh); cudaGetSymbolAddress((void**)&combl, g_combl);
    cudaGetSymbolAddress((void**)&xah, g_xah);   cudaGetSymbolAddress((void**)&xal, g_xal);
    cudaGetSymbolAddress((void**)&sph, g_sph);
    cudaGetSymbolAddress((void**)&tffh, g_tffh); cudaGetSymbolAddress((void**)&tffl, g_tffl);

    bf16 *wqh,*wql,*wkh,*wkl,*wvh,*wvl,*woh,*wol,*wsh,*wsl,*w1h,*w1l,*w2h,*w2l,*wouth,*woutl;
    cudaGetSymbolAddress((void**)&wqh, g_wqh);   cudaGetSymbolAddress((void**)&wql, g_wql);
    cudaGetSymbolAddress((void**)&wkh, g_wkh);   cudaGetSymbolAddress((void**)&wkl, g_wkl);
    cudaGetSymbolAddress((void**)&wvh, g_wvh);   cudaGetSymbolAddress((void**)&wvl, g_wvl);
    cudaGetSymbolAddress((void**)&woh, g_woh);   cudaGetSymbolAddress((void**)&wol, g_wol);
    cudaGetSymbolAddress((void**)&wsh, g_wsh);   cudaGetSymbolAddress((void**)&wsl, g_wsl);
    cudaGetSymbolAddress((void**)&w1h, g_w1h);   cudaGetSymbolAddress((void**)&w1l, g_w1l);
    cudaGetSymbolAddress((void**)&w2h, g_w2h);   cudaGetSymbolAddress((void**)&w2l, g_w2l);
    cudaGetSymbolAddress((void**)&wouth, g_wouth); cudaGetSymbolAddress((void**)&woutl, g_woutl);

    // ---- weight pre-split (memory-bound) ----
    const int NW = L_*D_*D_;
    const int NF = L_*D_*FF_;
    cvtw_kernel<<<NW/1024, 256>>>(Wq, wqh, wql, NW);
    cvtw_kernel<<<NW/1024, 256>>>(Wk, wkh, wkl, NW);
    cvtw_kernel<<<NW/1024, 256>>>(Wv, wvh, wvl, NW);
    cvtw_kernel<<<NW/1024, 256>>>(Wo, woh, wol, NW);
    cvtw_kernel<<<NW/1024, 256>>>(Wsnn, wsh, wsl, NW);
    cvtw_kernel<<<NF/1024, 256>>>(W1, w1h, w1l, NF);
    cvtw_kernel<<<NF/1024, 256>>>(W2, w2h, w2l, NF);
    cvtwout_kernel<<<dim3(NPV_/256, D_), 256>>>(Wout, wouth, woutl);

    embed_kernel<<<SB_, 256>>>(src, emb, x0, x0h, x0l);
    dw_kernel<<<1, 32>>>(lw, dw);

    for (int l = 0; l < L_; l++) {
        int nsrc = (l == 0) ? 1 : l;
        const bf16* sbh = (l == 0) ? x0h : loh;
        const bf16* sbl = (l == 0) ? x0l : lol;
        const bf16* xinh = (l == 0) ? x0h : (loh + (size_t)(l-1)*SBD_);
        const bf16* xinl = (l == 0) ? x0l : (lol + (size_t)(l-1)*SBD_);
        const float* xinf = (l == 0) ? x0 : (lo + (size_t)(l-1)*SBD_);

        // K, V (all distinct sources) -> planes; Q split-K=2 -> partials -> planes
        gemm_wmma<1,false,false,false><<<dim3(D_/128, nsrc*4), 256>>>(
            D_, D_, sbh, sbl, D_, wkh + (size_t)l*D_*D_, wkl + (size_t)l*D_*D_, D_,
            bk + l*D_, nullptr, kh, kl, D_);
        gemm_wmma<1,false,false,false><<<dim3(D_/128, nsrc*4), 256>>>(
            D_, D_, sbh, sbl, D_, wvh + (size_t)l*D_*D_, wvl + (size_t)l*D_*D_, D_,
            bv + l*D_, nullptr, vh, vl, D_);
        gemm_wmma_sk<<<dim3(D_/128, SB_/128, 2), 256>>>(
            D_, D_/2, xinh, xinl, D_, wqh + (size_t)l*D_*D_, wql + (size_t)l*D_*D_, D_,
            bq + l*D_, t2, D_, SBD_);
        cvt2_kernel<<<SBD_/1024, 256>>>(t2, t2b, qh, ql);

        qk_wmma<<<dim3(2, 2, nsrc*16), 256>>>(qh, ql, kh, kl, sc);
        softmax_kernel<<<nsrc*512, 256>>>(sc, sch, scl, dw + l*16);

        // chunked comb (2 sources/chunk): fp32 atomic accumulate -> planes
        cudaMemsetAsync(cmbf, 0, SBD_*sizeof(float));
        int nchunk = (nsrc + 1) / 2;
        comb_wmma<<<dim3(1, 2, 16*nchunk), 256>>>(nsrc, sch, scl, vh, vl, cmbf);
        cvtw_kernel<<<SBD_/1024, 256>>>(cmbf, combh, combl, SBD_);

        // Wo projection split-K=2 -> partials; add+LN(2) -> xa fp32 + planes
        gemm_wmma_sk<<<dim3(D_/128, SB_/128, 2), 256>>>(
            D_, D_/2, combh, combl, D_, woh + (size_t)l*D_*D_, wol + (size_t)l*D_*D_, D_,
            bo + l*D_, t2, D_, SBD_);
        addln_kernel<2><<<SB_, 256>>>(xinf, t2, SBD_, g1 + l*D_, be1 + l*D_, xa, xah, xal);

        // SNN projection split-K=2 -> partials; scan sums them -> bf16 spikes
        gemm_wmma_sk<<<dim3(D_/128, SB_/128, 2), 256>>>(
            D_, D_/2, xah, xal, D_, wsh + (size_t)l*D_*D_, wsl + (size_t)l*D_*D_, D_,
            bsnn + l*D_, t2, D_, SBD_);
        snn_kernel<<<B_, 256>>>(t2, t2b, sph);

        // FFN: FF1 (A exact bf16, ReLU) -> planes; FF2 split-K=4; add+LN(4) -> lo[l]
        gemm_wmma<1,true,false,true><<<dim3(FF_/128, SB_/128), 256>>>(
            FF_, D_, sph, sph, D_, w1h + (size_t)l*D_*FF_, w1l + (size_t)l*D_*FF_, FF_,
            b1 + l*FF_, nullptr, tffh, tffl, FF_);
        gemm_wmma_sk<<<dim3(D_/128, SB_/128, 4), 256>>>(
            D_, FF_/4, tffh, tffl, FF_, w2h + (size_t)l*FF_*D_, w2l + (size_t)l*FF_*D_, D_,
            b2 + l*D_, t2, D_, SBD_);
        addln_kernel<4><<<SB_, 256>>>(xa, t2, SBD_, g2 + l*D_, be2 + l*D_,
                                      lo + (size_t)l*SBD_,
                                      loh + (size_t)l*SBD_, lol + (size_t)l*SBD_);
    }

    // final vocab projection (fp32 out, fused [S,B]->[B,S] transpose)
    gemm_wmma<0,false,true,false><<<dim3((V_+127)/128, SB_/128), 256>>>(
        V_, D_, loh + (size_t)15*SBD_, lol + (size_t)15*SBD_, D_,
        wouth, woutl, NPV_, bout, out, nullptr, nullptr, V_);
}